// round 2
// baseline (speedup 1.0000x reference)
#include <cuda_runtime.h>
#include <math.h>

// Problem constants
#define B_   8
#define LQ_  2048
#define LK_  2048
#define DIN_ 128
#define DO_  64

// Tiles
#define BQ 64
#define BC 64
#define PAD 68   // padded row stride (floats): 68*4=272B, 16B-aligned, bank-safe

// Scratch for projected q/k/v (static device arrays: allocation-guard safe)
__device__ float g_q[B_ * LQ_ * DO_];
__device__ float g_k[B_ * LK_ * DO_];
__device__ float g_v[B_ * LK_ * DO_];

// ---------------------------------------------------------------------------
// Projection: out[M, 64] = A[M, 128] @ W[128, 64]
// Block = 64 rows, 256 threads, 4x4 register tile per thread, K-tiled by 32.
// ---------------------------------------------------------------------------
__global__ __launch_bounds__(256) void proj_kernel(
    const float* __restrict__ A, const float* __restrict__ W,
    float* __restrict__ out)
{
    __shared__ __align__(16) float At[32][PAD];  // At[k][row]
    __shared__ __align__(16) float Ws[32][PAD];  // Ws[k][col]

    const int tid = threadIdx.x;
    const int ty = tid >> 4;       // 0..15 (row group)
    const int tx = tid & 15;       // 0..15 (col group)
    const size_t row0 = (size_t)blockIdx.x * BQ;

    float acc[4][4];
#pragma unroll
    for (int i = 0; i < 4; i++)
#pragma unroll
        for (int j = 0; j < 4; j++) acc[i][j] = 0.f;

    for (int k0 = 0; k0 < DIN_; k0 += 32) {
        // Load A tile [64 x 32] transposed into At[k][row]
#pragma unroll
        for (int i = tid; i < 64 * 32; i += 256) {
            int r = i >> 5, c = i & 31;
            At[c][r] = A[(row0 + r) * DIN_ + k0 + c];
        }
        // Load W tile [32 x 64] into Ws[k][col]
#pragma unroll
        for (int i = tid; i < 32 * 64; i += 256) {
            int r = i >> 6, c = i & 63;
            Ws[r][c] = W[(k0 + r) * DO_ + c];
        }
        __syncthreads();
#pragma unroll 8
        for (int kk = 0; kk < 32; kk++) {
            float4 a4 = *(const float4*)&At[kk][4 * ty];
            float4 b4 = *(const float4*)&Ws[kk][4 * tx];
            float av[4] = {a4.x, a4.y, a4.z, a4.w};
            float bv[4] = {b4.x, b4.y, b4.z, b4.w};
#pragma unroll
            for (int i = 0; i < 4; i++)
#pragma unroll
                for (int j = 0; j < 4; j++)
                    acc[i][j] = fmaf(av[i], bv[j], acc[i][j]);
        }
        __syncthreads();
    }

#pragma unroll
    for (int i = 0; i < 4; i++)
#pragma unroll
        for (int j = 0; j < 4; j++)
            out[(row0 + 4 * ty + i) * DO_ + 4 * tx + j] = acc[i][j];
}

// ---------------------------------------------------------------------------
// Fused flash attention (unscaled scores, softmax over Lk, then @ V).
// Grid: (Lq/64, B). Block: 256 threads. Online softmax, fp32 throughout.
// ---------------------------------------------------------------------------
__global__ __launch_bounds__(256) void attn_kernel(
    const float* __restrict__ q, const float* __restrict__ k,
    const float* __restrict__ v, float* __restrict__ out)
{
    extern __shared__ __align__(16) float sm[];
    float* Qt = sm;                  // [64][PAD]  Qt[d][qrow]
    float* Kt = Qt + 64 * PAD;       // [64][PAD]  Kt[d][krow]
    float* Vs = Kt + 64 * PAD;       // [64][PAD]  Vs[krow][c]
    float* Pt = Vs + 64 * PAD;       // [64][PAD]  Pt[krow][qrow]

    const int tid = threadIdx.x;
    const int ty = tid >> 4;   // q-row group
    const int tx = tid & 15;   // col group
    const int b  = blockIdx.y;
    const size_t q0 = (size_t)blockIdx.x * BQ;

    const float* qb = q + ((size_t)b * LQ_ + q0) * DO_;
    const float* kb = k + (size_t)b * LK_ * DO_;
    const float* vb = v + (size_t)b * LK_ * DO_;

    // Load Q tile transposed: Qt[d][r]
#pragma unroll
    for (int i = tid; i < 64 * 64; i += 256) {
        int r = i >> 6, d = i & 63;
        Qt[d * PAD + r] = qb[(size_t)r * DO_ + d];
    }

    float m[4], l[4], acc[4][4];
#pragma unroll
    for (int i = 0; i < 4; i++) {
        m[i] = -1e30f; l[i] = 0.f;
#pragma unroll
        for (int j = 0; j < 4; j++) acc[i][j] = 0.f;
    }

    for (int kt = 0; kt < LK_; kt += BC) {
        __syncthreads();   // previous iter's PV reads of Vs/Pt done; Qt load done (iter 0)
        // Load K tile transposed Kt[d][j] and V tile natural Vs[j][c]
#pragma unroll
        for (int i = tid; i < 64 * 64; i += 256) {
            int r = i >> 6, d = i & 63;
            float kv = kb[(size_t)(kt + r) * DO_ + d];
            float vv = vb[(size_t)(kt + r) * DO_ + d];
            Kt[d * PAD + r] = kv;
            Vs[r * PAD + d] = vv;
        }
        __syncthreads();

        // S = Q @ K^T  (4x4 per thread)
        float s[4][4];
#pragma unroll
        for (int i = 0; i < 4; i++)
#pragma unroll
            for (int j = 0; j < 4; j++) s[i][j] = 0.f;
#pragma unroll 8
        for (int kk = 0; kk < 64; kk++) {
            float4 a4 = *(const float4*)(Qt + kk * PAD + 4 * ty);
            float4 b4 = *(const float4*)(Kt + kk * PAD + 4 * tx);
            float av[4] = {a4.x, a4.y, a4.z, a4.w};
            float bv[4] = {b4.x, b4.y, b4.z, b4.w};
#pragma unroll
            for (int i = 0; i < 4; i++)
#pragma unroll
                for (int j = 0; j < 4; j++)
                    s[i][j] = fmaf(av[i], bv[j], s[i][j]);
        }

        // Online softmax per q-row. Row group = 16 lanes sharing ty
        // (lanes 0-15 or 16-31 of a warp) -> xor-shuffle over 8,4,2,1.
#pragma unroll
        for (int i = 0; i < 4; i++) {
            float rm = fmaxf(fmaxf(s[i][0], s[i][1]), fmaxf(s[i][2], s[i][3]));
#pragma unroll
            for (int off = 8; off >= 1; off >>= 1)
                rm = fmaxf(rm, __shfl_xor_sync(0xffffffffu, rm, off));
            float mn = fmaxf(m[i], rm);
            float sc = __expf(m[i] - mn);
            float rs = 0.f;
#pragma unroll
            for (int j = 0; j < 4; j++) {
                float p = __expf(s[i][j] - mn);
                s[i][j] = p;
                rs += p;
            }
#pragma unroll
            for (int off = 8; off >= 1; off >>= 1)
                rs += __shfl_xor_sync(0xffffffffu, rs, off);
            l[i] = l[i] * sc + rs;
            m[i] = mn;
#pragma unroll
            for (int j = 0; j < 4; j++) acc[i][j] *= sc;
        }

        // Write P transposed: Pt[kcol][qrow]
#pragma unroll
        for (int j = 0; j < 4; j++)
#pragma unroll
            for (int i = 0; i < 4; i++)
                Pt[(4 * tx + j) * PAD + (4 * ty + i)] = s[i][j];
        __syncthreads();

        // O += P @ V
#pragma unroll 8
        for (int jj = 0; jj < 64; jj++) {
            float4 a4 = *(const float4*)(Pt + jj * PAD + 4 * ty);
            float4 b4 = *(const float4*)(Vs + jj * PAD + 4 * tx);
            float av[4] = {a4.x, a4.y, a4.z, a4.w};
            float bv[4] = {b4.x, b4.y, b4.z, b4.w};
#pragma unroll
            for (int i = 0; i < 4; i++)
#pragma unroll
                for (int j = 0; j < 4; j++)
                    acc[i][j] = fmaf(av[i], bv[j], acc[i][j]);
        }
    }

    // Normalize and write out
    float* ob = out + ((size_t)b * LQ_ + q0) * DO_;
#pragma unroll
    for (int i = 0; i < 4; i++) {
        float inv = 1.0f / l[i];
#pragma unroll
        for (int j = 0; j < 4; j++)
            ob[(size_t)(4 * ty + i) * DO_ + 4 * tx + j] = acc[i][j] * inv;
    }
}

// ---------------------------------------------------------------------------
// kernel_launch
// ---------------------------------------------------------------------------
extern "C" void kernel_launch(void* const* d_in, const int* in_sizes, int n_in,
                              void* d_out, int out_size)
{
    const float* query = (const float*)d_in[0];
    const float* key   = (const float*)d_in[1];
    const float* Wq    = (const float*)d_in[2];
    const float* Wk    = (const float*)d_in[3];
    const float* Wv    = (const float*)d_in[4];
    float* out = (float*)d_out;

    float *gq, *gk, *gv;
    cudaGetSymbolAddress((void**)&gq, g_q);
    cudaGetSymbolAddress((void**)&gk, g_k);
    cudaGetSymbolAddress((void**)&gv, g_v);

    const int M = B_ * LQ_;            // 16384 rows for q-proj (Lk same for k/v)
    const int projBlocks = M / BQ;     // 256

    proj_kernel<<<projBlocks, 256>>>(query, Wq, gq);
    proj_kernel<<<projBlocks, 256>>>(key,   Wk, gk);
    proj_kernel<<<projBlocks, 256>>>(key,   Wv, gv);

    const int smemBytes = 4 * 64 * PAD * sizeof(float);   // 69,632 B
    cudaFuncSetAttribute(attn_kernel,
                         cudaFuncAttributeMaxDynamicSharedMemorySize, smemBytes);
    dim3 grid(LQ_ / BQ, B_);   // (32, 8)
    attn_kernel<<<grid, 256, smemBytes>>>(gq, gk, gv, out);
}

// round 3
// speedup vs baseline: 1.0402x; 1.0402x over previous
#include <cuda_runtime.h>
#include <math.h>

// Problem constants
#define B_   8
#define LQ_  2048
#define LK_  2048
#define DIN_ 128
#define DO_  64

// Tiles
#define BQ 64
#define BC 64
#define PAD 68   // padded row stride (floats): 272B, 16B-aligned

// Scratch for projected q/k/v
__device__ float g_q[B_ * LQ_ * DO_];
__device__ float g_k[B_ * LK_ * DO_];
__device__ float g_v[B_ * LK_ * DO_];

// ---------------------------------------------------------------------------
// Q projection: out[M,64] = A[M,128] @ W[128,64]
// 64 rows/block, 256 threads, 4x4 tile (unchanged from R1 — small share of time)
// ---------------------------------------------------------------------------
__global__ __launch_bounds__(256) void proj_kernel(
    const float* __restrict__ A, const float* __restrict__ W,
    float* __restrict__ out)
{
    __shared__ __align__(16) float At[32][PAD];
    __shared__ __align__(16) float Ws[32][PAD];

    const int tid = threadIdx.x;
    const int ty = tid >> 4;
    const int tx = tid & 15;
    const size_t row0 = (size_t)blockIdx.x * BQ;

    float acc[4][4];
#pragma unroll
    for (int i = 0; i < 4; i++)
#pragma unroll
        for (int j = 0; j < 4; j++) acc[i][j] = 0.f;

    for (int k0 = 0; k0 < DIN_; k0 += 32) {
#pragma unroll
        for (int i = tid; i < 64 * 32; i += 256) {
            int r = i >> 5, c = i & 31;
            At[c][r] = A[(row0 + r) * DIN_ + k0 + c];
        }
#pragma unroll
        for (int i = tid; i < 32 * 64; i += 256) {
            int r = i >> 6, c = i & 63;
            Ws[r][c] = W[(k0 + r) * DO_ + c];
        }
        __syncthreads();
#pragma unroll 8
        for (int kk = 0; kk < 32; kk++) {
            float4 a4 = *(const float4*)&At[kk][4 * ty];
            float4 b4 = *(const float4*)&Ws[kk][4 * tx];
            float av[4] = {a4.x, a4.y, a4.z, a4.w};
            float bv[4] = {b4.x, b4.y, b4.z, b4.w};
#pragma unroll
            for (int i = 0; i < 4; i++)
#pragma unroll
                for (int j = 0; j < 4; j++)
                    acc[i][j] = fmaf(av[i], bv[j], acc[i][j]);
        }
        __syncthreads();
    }
#pragma unroll
    for (int i = 0; i < 4; i++)
#pragma unroll
        for (int j = 0; j < 4; j++)
            out[(row0 + 4 * ty + i) * DO_ + 4 * tx + j] = acc[i][j];
}

// ---------------------------------------------------------------------------
// Fused K+V projection: reads `key` tile once, produces both projections.
// ---------------------------------------------------------------------------
__global__ __launch_bounds__(256) void proj_kv_kernel(
    const float* __restrict__ A, const float* __restrict__ Wk,
    const float* __restrict__ Wv, float* __restrict__ outK,
    float* __restrict__ outV)
{
    __shared__ __align__(16) float At[32][PAD];
    __shared__ __align__(16) float Wks[32][PAD];
    __shared__ __align__(16) float Wvs[32][PAD];

    const int tid = threadIdx.x;
    const int ty = tid >> 4;
    const int tx = tid & 15;
    const size_t row0 = (size_t)blockIdx.x * BQ;

    float ak[4][4], av_[4][4];
#pragma unroll
    for (int i = 0; i < 4; i++)
#pragma unroll
        for (int j = 0; j < 4; j++) { ak[i][j] = 0.f; av_[i][j] = 0.f; }

    for (int k0 = 0; k0 < DIN_; k0 += 32) {
#pragma unroll
        for (int i = tid; i < 64 * 32; i += 256) {
            int r = i >> 5, c = i & 31;
            At[c][r] = A[(row0 + r) * DIN_ + k0 + c];
        }
#pragma unroll
        for (int i = tid; i < 32 * 64; i += 256) {
            int r = i >> 6, c = i & 63;
            Wks[r][c] = Wk[(k0 + r) * DO_ + c];
            Wvs[r][c] = Wv[(k0 + r) * DO_ + c];
        }
        __syncthreads();
#pragma unroll 8
        for (int kk = 0; kk < 32; kk++) {
            float4 a4 = *(const float4*)&At[kk][4 * ty];
            float4 bk = *(const float4*)&Wks[kk][4 * tx];
            float4 bv = *(const float4*)&Wvs[kk][4 * tx];
            float avv[4] = {a4.x, a4.y, a4.z, a4.w};
            float bkv[4] = {bk.x, bk.y, bk.z, bk.w};
            float bvv[4] = {bv.x, bv.y, bv.z, bv.w};
#pragma unroll
            for (int i = 0; i < 4; i++)
#pragma unroll
                for (int j = 0; j < 4; j++) {
                    ak[i][j]  = fmaf(avv[i], bkv[j], ak[i][j]);
                    av_[i][j] = fmaf(avv[i], bvv[j], av_[i][j]);
                }
        }
        __syncthreads();
    }
#pragma unroll
    for (int i = 0; i < 4; i++)
#pragma unroll
        for (int j = 0; j < 4; j++) {
            outK[(row0 + 4 * ty + i) * DO_ + 4 * tx + j] = ak[i][j];
            outV[(row0 + 4 * ty + i) * DO_ + 4 * tx + j] = av_[i][j];
        }
}

// ---------------------------------------------------------------------------
// Fused flash attention. 128 threads, BQ=BC=64, 8x4 thread tile.
// Per k-step: 3x LDS.128 per 32 FFMA -> FMA-pipe-bound.
// ---------------------------------------------------------------------------
__global__ __launch_bounds__(128) void attn_kernel(
    const float* __restrict__ q, const float* __restrict__ k,
    const float* __restrict__ v, float* __restrict__ out)
{
    extern __shared__ __align__(16) float sm[];
    float* Qt = sm;                  // [64][PAD]  Qt[d][qrow]
    float* Kt = Qt + 64 * PAD;       // [64][PAD]  Kt[d][krow]
    float* Vs = Kt + 64 * PAD;       // [64][PAD]  Vs[krow][c]
    float* Pt = Vs + 64 * PAD;       // [64][PAD]  Pt[krow][qrow]

    const int tid = threadIdx.x;
    const int ty = tid >> 4;   // 0..7  (8 q-rows each)
    const int tx = tid & 15;   // 0..15 (4 cols each)
    const int b  = blockIdx.y;
    const size_t q0 = (size_t)blockIdx.x * BQ;

    const float* qb = q + ((size_t)b * LQ_ + q0) * DO_;
    const float* kb = k + (size_t)b * LK_ * DO_;
    const float* vb = v + (size_t)b * LK_ * DO_;

    // Load Q tile transposed: Qt[d][r]
#pragma unroll
    for (int i = tid; i < 64 * 64; i += 128) {
        int r = i >> 6, d = i & 63;
        Qt[d * PAD + r] = qb[(size_t)r * DO_ + d];
    }

    float m[8], l[8], acc[8][4];
#pragma unroll
    for (int i = 0; i < 8; i++) {
        m[i] = -1e30f; l[i] = 0.f;
#pragma unroll
        for (int j = 0; j < 4; j++) acc[i][j] = 0.f;
    }

    for (int kt = 0; kt < LK_; kt += BC) {
        __syncthreads();   // prior PV reads of Kt/Vs done (and Qt load, iter 0)
#pragma unroll
        for (int i = tid; i < 64 * 64; i += 128) {
            int r = i >> 6, d = i & 63;
            Kt[d * PAD + r] = kb[(size_t)(kt + r) * DO_ + d];
            Vs[r * PAD + d] = vb[(size_t)(kt + r) * DO_ + d];
        }
        __syncthreads();

        // S = Q @ K^T : 8x4 per thread
        float s[8][4];
#pragma unroll
        for (int i = 0; i < 8; i++)
#pragma unroll
            for (int j = 0; j < 4; j++) s[i][j] = 0.f;
#pragma unroll 8
        for (int kk = 0; kk < 64; kk++) {
            float4 a0 = *(const float4*)(Qt + kk * PAD + 8 * ty);
            float4 a1 = *(const float4*)(Qt + kk * PAD + 8 * ty + 4);
            float4 b4 = *(const float4*)(Kt + kk * PAD + 4 * tx);
            float av[8] = {a0.x, a0.y, a0.z, a0.w, a1.x, a1.y, a1.z, a1.w};
            float bv[4] = {b4.x, b4.y, b4.z, b4.w};
#pragma unroll
            for (int i = 0; i < 8; i++)
#pragma unroll
                for (int j = 0; j < 4; j++)
                    s[i][j] = fmaf(av[i], bv[j], s[i][j]);
        }

        // Online softmax, per q-row. 16 lanes (same ty) hold a row: xor 8..1.
#pragma unroll
        for (int i = 0; i < 8; i++) {
            float rm = fmaxf(fmaxf(s[i][0], s[i][1]), fmaxf(s[i][2], s[i][3]));
#pragma unroll
            for (int off = 8; off >= 1; off >>= 1)
                rm = fmaxf(rm, __shfl_xor_sync(0xffffffffu, rm, off));
            float mn = fmaxf(m[i], rm);
            float sc = __expf(m[i] - mn);
            float rs = 0.f;
#pragma unroll
            for (int j = 0; j < 4; j++) {
                float p = __expf(s[i][j] - mn);
                s[i][j] = p;
                rs += p;
            }
#pragma unroll
            for (int off = 8; off >= 1; off >>= 1)
                rs += __shfl_xor_sync(0xffffffffu, rs, off);
            l[i] = l[i] * sc + rs;
            m[i] = mn;
#pragma unroll
            for (int j = 0; j < 4; j++) acc[i][j] *= sc;
        }

        // Pt[kcol][qrow], vectorized: two float4 per owned column
#pragma unroll
        for (int j = 0; j < 4; j++) {
            float4 lo = make_float4(s[0][j], s[1][j], s[2][j], s[3][j]);
            float4 hi = make_float4(s[4][j], s[5][j], s[6][j], s[7][j]);
            *(float4*)(Pt + (4 * tx + j) * PAD + 8 * ty)     = lo;
            *(float4*)(Pt + (4 * tx + j) * PAD + 8 * ty + 4) = hi;
        }
        __syncthreads();

        // O += P @ V
#pragma unroll 8
        for (int jj = 0; jj < 64; jj++) {
            float4 a0 = *(const float4*)(Pt + jj * PAD + 8 * ty);
            float4 a1 = *(const float4*)(Pt + jj * PAD + 8 * ty + 4);
            float4 b4 = *(const float4*)(Vs + jj * PAD + 4 * tx);
            float av[8] = {a0.x, a0.y, a0.z, a0.w, a1.x, a1.y, a1.z, a1.w};
            float bv[4] = {b4.x, b4.y, b4.z, b4.w};
#pragma unroll
            for (int i = 0; i < 8; i++)
#pragma unroll
                for (int j = 0; j < 4; j++)
                    acc[i][j] = fmaf(av[i], bv[j], acc[i][j]);
        }
    }

    // Normalize + store
    float* ob = out + ((size_t)b * LQ_ + q0) * DO_;
#pragma unroll
    for (int i = 0; i < 8; i++) {
        float inv = 1.0f / l[i];
#pragma unroll
        for (int j = 0; j < 4; j++)
            ob[(size_t)(8 * ty + i) * DO_ + 4 * tx + j] = acc[i][j] * inv;
    }
}

// ---------------------------------------------------------------------------
extern "C" void kernel_launch(void* const* d_in, const int* in_sizes, int n_in,
                              void* d_out, int out_size)
{
    const float* query = (const float*)d_in[0];
    const float* key   = (const float*)d_in[1];
    const float* Wq    = (const float*)d_in[2];
    const float* Wk    = (const float*)d_in[3];
    const float* Wv    = (const float*)d_in[4];
    float* out = (float*)d_out;

    float *gq, *gk, *gv;
    cudaGetSymbolAddress((void**)&gq, g_q);
    cudaGetSymbolAddress((void**)&gk, g_k);
    cudaGetSymbolAddress((void**)&gv, g_v);

    const int M = B_ * LQ_;
    const int projBlocks = M / BQ;    // 256

    proj_kernel<<<projBlocks, 256>>>(query, Wq, gq);
    proj_kv_kernel<<<projBlocks, 256>>>(key, Wk, Wv, gk, gv);

    const int smemBytes = 4 * 64 * PAD * sizeof(float);   // 69,632 B
    cudaFuncSetAttribute(attn_kernel,
                         cudaFuncAttributeMaxDynamicSharedMemorySize, smemBytes);
    dim3 grid(LQ_ / BQ, B_);   // (32, 8)
    attn_kernel<<<grid, 128, smemBytes>>>(gq, gk, gv, out);
}

// round 4
// speedup vs baseline: 1.1873x; 1.1414x over previous
#include <cuda_runtime.h>
#include <math.h>

// Problem constants
#define B_   8
#define LQ_  2048
#define LK_  2048
#define DIN_ 128
#define DO_  64

// Tiles
#define BQ 64
#define BC 64
#define PAD 68   // padded row stride (floats): 272B, 16B-aligned

typedef unsigned long long u64;

// ---- packed f32x2 helpers (Blackwell FFMA2 path) --------------------------
__device__ __forceinline__ u64 pk2(float lo, float hi) {
    u64 r; asm("mov.b64 %0, {%1, %2};" : "=l"(r) : "f"(lo), "f"(hi)); return r;
}
__device__ __forceinline__ void upk2(u64 v, float& lo, float& hi) {
    asm("mov.b64 {%0, %1}, %2;" : "=f"(lo), "=f"(hi) : "l"(v));
}
__device__ __forceinline__ u64 ffma2(u64 a, u64 b, u64 c) {
    u64 d; asm("fma.rn.f32x2 %0, %1, %2, %3;" : "=l"(d) : "l"(a), "l"(b), "l"(c));
    return d;
}
__device__ __forceinline__ u64 fmul2(u64 a, u64 b) {
    u64 d; asm("mul.rn.f32x2 %0, %1, %2;" : "=l"(d) : "l"(a), "l"(b)); return d;
}

// Scratch for projected q/k/v
__device__ float g_q[B_ * LQ_ * DO_];
__device__ float g_k[B_ * LK_ * DO_];
__device__ float g_v[B_ * LK_ * DO_];

// ---------------------------------------------------------------------------
// Q projection: out[M,64] = A[M,128] @ W[128,64], f32x2 accumulators
// ---------------------------------------------------------------------------
__global__ __launch_bounds__(256) void proj_kernel(
    const float* __restrict__ A, const float* __restrict__ W,
    float* __restrict__ out)
{
    __shared__ __align__(16) float At[32][PAD];
    __shared__ __align__(16) float Ws[32][PAD];

    const int tid = threadIdx.x;
    const int ty = tid >> 4;
    const int tx = tid & 15;
    const size_t row0 = (size_t)blockIdx.x * BQ;

    u64 acc2[2][4];
#pragma unroll
    for (int i = 0; i < 2; i++)
#pragma unroll
        for (int j = 0; j < 4; j++) acc2[i][j] = 0ull;

    for (int k0 = 0; k0 < DIN_; k0 += 32) {
#pragma unroll
        for (int i = tid; i < 64 * 32; i += 256) {
            int r = i >> 5, c = i & 31;
            At[c][r] = A[(row0 + r) * DIN_ + k0 + c];
        }
#pragma unroll
        for (int i = tid; i < 32 * 64; i += 256) {
            int r = i >> 6, c = i & 63;
            Ws[r][c] = W[(k0 + r) * DO_ + c];
        }
        __syncthreads();
#pragma unroll 8
        for (int kk = 0; kk < 32; kk++) {
            ulonglong2 a2 = *(const ulonglong2*)&At[kk][4 * ty];
            float4 b4 = *(const float4*)&Ws[kk][4 * tx];
            u64 ap[2] = {a2.x, a2.y};
            u64 bp[4] = {pk2(b4.x, b4.x), pk2(b4.y, b4.y),
                         pk2(b4.z, b4.z), pk2(b4.w, b4.w)};
#pragma unroll
            for (int i = 0; i < 2; i++)
#pragma unroll
                for (int j = 0; j < 4; j++)
                    acc2[i][j] = ffma2(ap[i], bp[j], acc2[i][j]);
        }
        __syncthreads();
    }
#pragma unroll
    for (int i = 0; i < 2; i++)
#pragma unroll
        for (int j = 0; j < 4; j++) {
            float lo, hi;
            upk2(acc2[i][j], lo, hi);
            out[(row0 + 4 * ty + 2 * i + 0) * DO_ + 4 * tx + j] = lo;
            out[(row0 + 4 * ty + 2 * i + 1) * DO_ + 4 * tx + j] = hi;
        }
}

// ---------------------------------------------------------------------------
// Fused K+V projection, f32x2 accumulators
// ---------------------------------------------------------------------------
__global__ __launch_bounds__(256) void proj_kv_kernel(
    const float* __restrict__ A, const float* __restrict__ Wk,
    const float* __restrict__ Wv, float* __restrict__ outK,
    float* __restrict__ outV)
{
    __shared__ __align__(16) float At[32][PAD];
    __shared__ __align__(16) float Wks[32][PAD];
    __shared__ __align__(16) float Wvs[32][PAD];

    const int tid = threadIdx.x;
    const int ty = tid >> 4;
    const int tx = tid & 15;
    const size_t row0 = (size_t)blockIdx.x * BQ;

    u64 ak2[2][4], av2[2][4];
#pragma unroll
    for (int i = 0; i < 2; i++)
#pragma unroll
        for (int j = 0; j < 4; j++) { ak2[i][j] = 0ull; av2[i][j] = 0ull; }

    for (int k0 = 0; k0 < DIN_; k0 += 32) {
#pragma unroll
        for (int i = tid; i < 64 * 32; i += 256) {
            int r = i >> 5, c = i & 31;
            At[c][r] = A[(row0 + r) * DIN_ + k0 + c];
        }
#pragma unroll
        for (int i = tid; i < 32 * 64; i += 256) {
            int r = i >> 6, c = i & 63;
            Wks[r][c] = Wk[(k0 + r) * DO_ + c];
            Wvs[r][c] = Wv[(k0 + r) * DO_ + c];
        }
        __syncthreads();
#pragma unroll 8
        for (int kk = 0; kk < 32; kk++) {
            ulonglong2 a2 = *(const ulonglong2*)&At[kk][4 * ty];
            float4 bk = *(const float4*)&Wks[kk][4 * tx];
            float4 bv = *(const float4*)&Wvs[kk][4 * tx];
            u64 ap[2] = {a2.x, a2.y};
            u64 bkp[4] = {pk2(bk.x, bk.x), pk2(bk.y, bk.y),
                          pk2(bk.z, bk.z), pk2(bk.w, bk.w)};
            u64 bvp[4] = {pk2(bv.x, bv.x), pk2(bv.y, bv.y),
                          pk2(bv.z, bv.z), pk2(bv.w, bv.w)};
#pragma unroll
            for (int i = 0; i < 2; i++)
#pragma unroll
                for (int j = 0; j < 4; j++) {
                    ak2[i][j] = ffma2(ap[i], bkp[j], ak2[i][j]);
                    av2[i][j] = ffma2(ap[i], bvp[j], av2[i][j]);
                }
        }
        __syncthreads();
    }
#pragma unroll
    for (int i = 0; i < 2; i++)
#pragma unroll
        for (int j = 0; j < 4; j++) {
            float klo, khi, vlo, vhi;
            upk2(ak2[i][j], klo, khi);
            upk2(av2[i][j], vlo, vhi);
            outK[(row0 + 4 * ty + 2 * i + 0) * DO_ + 4 * tx + j] = klo;
            outK[(row0 + 4 * ty + 2 * i + 1) * DO_ + 4 * tx + j] = khi;
            outV[(row0 + 4 * ty + 2 * i + 0) * DO_ + 4 * tx + j] = vlo;
            outV[(row0 + 4 * ty + 2 * i + 1) * DO_ + 4 * tx + j] = vhi;
        }
}

// ---------------------------------------------------------------------------
// Fused flash attention. 128 threads, BQ=BC=64, 8x4 thread tile,
// f32x2-packed GEMMs (row pairs in 64-bit regs).
// ---------------------------------------------------------------------------
__global__ __launch_bounds__(128) void attn_kernel(
    const float* __restrict__ q, const float* __restrict__ k,
    const float* __restrict__ v, float* __restrict__ out)
{
    extern __shared__ __align__(16) float sm[];
    float* Qt = sm;                  // [64][PAD]  Qt[d][qrow]
    float* Kt = Qt + 64 * PAD;       // [64][PAD]  Kt[d][krow]
    float* Vs = Kt + 64 * PAD;       // [64][PAD]  Vs[krow][c]
    float* Pt = Vs + 64 * PAD;       // [64][PAD]  Pt[krow][qrow]

    const int tid = threadIdx.x;
    const int ty = tid >> 4;   // 0..7  (8 q-rows each)
    const int tx = tid & 15;   // 0..15 (4 cols each)
    const int b  = blockIdx.y;
    const size_t q0 = (size_t)blockIdx.x * BQ;

    const float* qb = q + ((size_t)b * LQ_ + q0) * DO_;
    const float* kb = k + (size_t)b * LK_ * DO_;
    const float* vb = v + (size_t)b * LK_ * DO_;

    // Load Q tile transposed: Qt[d][r]
#pragma unroll
    for (int i = tid; i < 64 * 64; i += 128) {
        int r = i >> 6, d = i & 63;
        Qt[d * PAD + r] = qb[(size_t)r * DO_ + d];
    }

    float m[8], l[8];
    u64 acc2[4][4];   // row pairs (8*ty+2*ip, 8*ty+2*ip+1) x 4 cols
#pragma unroll
    for (int i = 0; i < 8; i++) { m[i] = -1e30f; l[i] = 0.f; }
#pragma unroll
    for (int i = 0; i < 4; i++)
#pragma unroll
        for (int j = 0; j < 4; j++) acc2[i][j] = 0ull;

    for (int kt = 0; kt < LK_; kt += BC) {
        __syncthreads();   // prior PV reads of Kt/Vs done (and Qt load, iter 0)
#pragma unroll
        for (int i = tid; i < 64 * 64; i += 128) {
            int r = i >> 6, d = i & 63;
            Kt[d * PAD + r] = kb[(size_t)(kt + r) * DO_ + d];
            Vs[r * PAD + d] = vb[(size_t)(kt + r) * DO_ + d];
        }
        __syncthreads();

        // S = Q @ K^T : packed row pairs
        u64 s2[4][4];
#pragma unroll
        for (int i = 0; i < 4; i++)
#pragma unroll
            for (int j = 0; j < 4; j++) s2[i][j] = 0ull;
#pragma unroll 8
        for (int kk = 0; kk < 64; kk++) {
            ulonglong2 qa0 = *(const ulonglong2*)(Qt + kk * PAD + 8 * ty);
            ulonglong2 qa1 = *(const ulonglong2*)(Qt + kk * PAD + 8 * ty + 4);
            float4 b4 = *(const float4*)(Kt + kk * PAD + 4 * tx);
            u64 ap[4] = {qa0.x, qa0.y, qa1.x, qa1.y};
            u64 bp[4] = {pk2(b4.x, b4.x), pk2(b4.y, b4.y),
                         pk2(b4.z, b4.z), pk2(b4.w, b4.w)};
#pragma unroll
            for (int ip = 0; ip < 4; ip++)
#pragma unroll
                for (int j = 0; j < 4; j++)
                    s2[ip][j] = ffma2(ap[ip], bp[j], s2[ip][j]);
        }

        // Unpack scores
        float s[8][4];
#pragma unroll
        for (int ip = 0; ip < 4; ip++)
#pragma unroll
            for (int j = 0; j < 4; j++)
                upk2(s2[ip][j], s[2 * ip][j], s[2 * ip + 1][j]);

        // Online softmax per q-row (16 lanes share a row: xor 8..1)
        float scl[8];
#pragma unroll
        for (int i = 0; i < 8; i++) {
            float rm = fmaxf(fmaxf(s[i][0], s[i][1]), fmaxf(s[i][2], s[i][3]));
#pragma unroll
            for (int off = 8; off >= 1; off >>= 1)
                rm = fmaxf(rm, __shfl_xor_sync(0xffffffffu, rm, off));
            float mn = fmaxf(m[i], rm);
            float sc = __expf(m[i] - mn);
            float rs = 0.f;
#pragma unroll
            for (int j = 0; j < 4; j++) {
                float p = __expf(s[i][j] - mn);
                s[i][j] = p;
                rs += p;
            }
#pragma unroll
            for (int off = 8; off >= 1; off >>= 1)
                rs += __shfl_xor_sync(0xffffffffu, rs, off);
            l[i] = l[i] * sc + rs;
            m[i] = mn;
            scl[i] = sc;
        }

        // Rescale accumulators (packed)
#pragma unroll
        for (int ip = 0; ip < 4; ip++) {
            u64 scp = pk2(scl[2 * ip], scl[2 * ip + 1]);
#pragma unroll
            for (int j = 0; j < 4; j++)
                acc2[ip][j] = fmul2(acc2[ip][j], scp);
        }

        // Pt[kcol][qrow], vectorized
#pragma unroll
        for (int j = 0; j < 4; j++) {
            float4 lo = make_float4(s[0][j], s[1][j], s[2][j], s[3][j]);
            float4 hi = make_float4(s[4][j], s[5][j], s[6][j], s[7][j]);
            *(float4*)(Pt + (4 * tx + j) * PAD + 8 * ty)     = lo;
            *(float4*)(Pt + (4 * tx + j) * PAD + 8 * ty + 4) = hi;
        }
        __syncthreads();

        // O += P @ V (packed row pairs)
#pragma unroll 8
        for (int jj = 0; jj < 64; jj++) {
            ulonglong2 pa0 = *(const ulonglong2*)(Pt + jj * PAD + 8 * ty);
            ulonglong2 pa1 = *(const ulonglong2*)(Pt + jj * PAD + 8 * ty + 4);
            float4 b4 = *(const float4*)(Vs + jj * PAD + 4 * tx);
            u64 ap[4] = {pa0.x, pa0.y, pa1.x, pa1.y};
            u64 bp[4] = {pk2(b4.x, b4.x), pk2(b4.y, b4.y),
                         pk2(b4.z, b4.z), pk2(b4.w, b4.w)};
#pragma unroll
            for (int ip = 0; ip < 4; ip++)
#pragma unroll
                for (int j = 0; j < 4; j++)
                    acc2[ip][j] = ffma2(ap[ip], bp[j], acc2[ip][j]);
        }
    }

    // Normalize + store
    float* ob = out + ((size_t)b * LQ_ + q0) * DO_;
#pragma unroll
    for (int ip = 0; ip < 4; ip++) {
        float inv0 = 1.0f / l[2 * ip];
        float inv1 = 1.0f / l[2 * ip + 1];
#pragma unroll
        for (int j = 0; j < 4; j++) {
            float lo, hi;
            upk2(acc2[ip][j], lo, hi);
            ob[(size_t)(8 * ty + 2 * ip + 0) * DO_ + 4 * tx + j] = lo * inv0;
            ob[(size_t)(8 * ty + 2 * ip + 1) * DO_ + 4 * tx + j] = hi * inv1;
        }
    }
}

// ---------------------------------------------------------------------------
extern "C" void kernel_launch(void* const* d_in, const int* in_sizes, int n_in,
                              void* d_out, int out_size)
{
    const float* query = (const float*)d_in[0];
    const float* key   = (const float*)d_in[1];
    const float* Wq    = (const float*)d_in[2];
    const float* Wk    = (const float*)d_in[3];
    const float* Wv    = (const float*)d_in[4];
    float* out = (float*)d_out;

    float *gq, *gk, *gv;
    cudaGetSymbolAddress((void**)&gq, g_q);
    cudaGetSymbolAddress((void**)&gk, g_k);
    cudaGetSymbolAddress((void**)&gv, g_v);

    const int M = B_ * LQ_;
    const int projBlocks = M / BQ;    // 256

    proj_kernel<<<projBlocks, 256>>>(query, Wq, gq);
    proj_kv_kernel<<<projBlocks, 256>>>(key, Wk, Wv, gk, gv);

    const int smemBytes = 4 * 64 * PAD * sizeof(float);   // 69,632 B
    cudaFuncSetAttribute(attn_kernel,
                         cudaFuncAttributeMaxDynamicSharedMemorySize, smemBytes);
    dim3 grid(LQ_ / BQ, B_);   // (32, 8)
    attn_kernel<<<grid, 128, smemBytes>>>(gq, gk, gv, out);
}

// round 7
// speedup vs baseline: 2.1170x; 1.7829x over previous
#include <cuda_runtime.h>
#include <cuda_bf16.h>
#include <math.h>
#include <stdint.h>

// Problem constants
#define B_   8
#define LQ_  2048
#define LK_  2048
#define DIN_ 128
#define DO_  64

#define PAD 68
typedef unsigned long long u64;

// ---- f32x2 helpers (projection kernels) -----------------------------------
__device__ __forceinline__ u64 pk2(float lo, float hi) {
    u64 r; asm("mov.b64 %0, {%1, %2};" : "=l"(r) : "f"(lo), "f"(hi)); return r;
}
__device__ __forceinline__ void upk2(u64 v, float& lo, float& hi) {
    asm("mov.b64 {%0, %1}, %2;" : "=f"(lo), "=f"(hi) : "l"(v));
}
__device__ __forceinline__ u64 ffma2(u64 a, u64 b, u64 c) {
    u64 d; asm("fma.rn.f32x2 %0, %1, %2, %3;" : "=l"(d) : "l"(a), "l"(b), "l"(c));
    return d;
}

// ---- tensor-core primitives (baseline PTX, sm_80+: OK for plain sm_103) ---
__device__ __forceinline__ void ldsm_x4(uint32_t* r, uint32_t addr) {
    asm volatile("ldmatrix.sync.aligned.m8n8.x4.shared.b16 {%0,%1,%2,%3}, [%4];"
        : "=r"(r[0]), "=r"(r[1]), "=r"(r[2]), "=r"(r[3]) : "r"(addr));
}
__device__ __forceinline__ void mma16816(float* d, const uint32_t* a,
                                         uint32_t b0, uint32_t b1) {
    asm volatile(
        "mma.sync.aligned.m16n8k16.row.col.f32.bf16.bf16.f32 "
        "{%0,%1,%2,%3}, {%4,%5,%6,%7}, {%8,%9}, {%0,%1,%2,%3};"
        : "+f"(d[0]), "+f"(d[1]), "+f"(d[2]), "+f"(d[3])
        : "r"(a[0]), "r"(a[1]), "r"(a[2]), "r"(a[3]), "r"(b0), "r"(b1));
}
__device__ __forceinline__ uint32_t smem_u32(const void* p) {
    uint32_t a;
    asm("{ .reg .u64 t; cvta.to.shared.u64 t, %1; cvt.u32.u64 %0, t; }"
        : "=r"(a) : "l"(p));
    return a;
}

// ---- Scratch: bf16 hi/lo splits -------------------------------------------
__device__ __nv_bfloat16 g_qh[B_ * LQ_ * DO_];
__device__ __nv_bfloat16 g_ql[B_ * LQ_ * DO_];
__device__ __nv_bfloat16 g_kh[B_ * LK_ * DO_];
__device__ __nv_bfloat16 g_kl[B_ * LK_ * DO_];
__device__ __nv_bfloat16 g_vth[B_ * DO_ * LK_];   // [b][dim][key] transposed
__device__ __nv_bfloat16 g_vtl[B_ * DO_ * LK_];

__device__ __forceinline__ void split_bf16(float x, __nv_bfloat16& h, __nv_bfloat16& l) {
    h = __float2bfloat16(x);
    l = __float2bfloat16(x - __bfloat162float(h));
}

// ---------------------------------------------------------------------------
// Q projection -> bf16 hi/lo, row-major [16384][64]
// ---------------------------------------------------------------------------
__global__ __launch_bounds__(256) void proj_q_kernel(
    const float* __restrict__ A, const float* __restrict__ W,
    __nv_bfloat16* __restrict__ oh, __nv_bfloat16* __restrict__ ol)
{
    __shared__ __align__(16) float At[32][PAD];
    __shared__ __align__(16) float Ws[32][PAD];

    const int tid = threadIdx.x;
    const int ty = tid >> 4, tx = tid & 15;
    const size_t row0 = (size_t)blockIdx.x * 64;

    u64 acc2[2][4];
#pragma unroll
    for (int i = 0; i < 2; i++)
#pragma unroll
        for (int j = 0; j < 4; j++) acc2[i][j] = 0ull;

    for (int k0 = 0; k0 < DIN_; k0 += 32) {
#pragma unroll
        for (int i = tid; i < 64 * 32; i += 256) {
            int r = i >> 5, c = i & 31;
            At[c][r] = A[(row0 + r) * DIN_ + k0 + c];
        }
#pragma unroll
        for (int i = tid; i < 32 * 64; i += 256) {
            int r = i >> 6, c = i & 63;
            Ws[r][c] = W[(k0 + r) * DO_ + c];
        }
        __syncthreads();
#pragma unroll 8
        for (int kk = 0; kk < 32; kk++) {
            ulonglong2 a2 = *(const ulonglong2*)&At[kk][4 * ty];
            float4 b4 = *(const float4*)&Ws[kk][4 * tx];
            u64 ap[2] = {a2.x, a2.y};
            u64 bp[4] = {pk2(b4.x, b4.x), pk2(b4.y, b4.y),
                         pk2(b4.z, b4.z), pk2(b4.w, b4.w)};
#pragma unroll
            for (int i = 0; i < 2; i++)
#pragma unroll
                for (int j = 0; j < 4; j++)
                    acc2[i][j] = ffma2(ap[i], bp[j], acc2[i][j]);
        }
        __syncthreads();
    }
#pragma unroll
    for (int i = 0; i < 2; i++)
#pragma unroll
        for (int j = 0; j < 4; j++) {
            float lo, hi;
            upk2(acc2[i][j], lo, hi);
            size_t r0 = row0 + 4 * ty + 2 * i;
            int c = 4 * tx + j;
            __nv_bfloat16 h, l;
            split_bf16(lo, h, l); oh[r0 * DO_ + c] = h; ol[r0 * DO_ + c] = l;
            split_bf16(hi, h, l); oh[(r0 + 1) * DO_ + c] = h; ol[(r0 + 1) * DO_ + c] = l;
        }
}

// ---------------------------------------------------------------------------
// Fused K+V projection -> K hi/lo row-major, V hi/lo TRANSPOSED [b][dim][key]
// ---------------------------------------------------------------------------
__global__ __launch_bounds__(256) void proj_kv_kernel(
    const float* __restrict__ A, const float* __restrict__ Wk,
    const float* __restrict__ Wv,
    __nv_bfloat16* __restrict__ okh, __nv_bfloat16* __restrict__ okl,
    __nv_bfloat16* __restrict__ ovh, __nv_bfloat16* __restrict__ ovl)
{
    __shared__ __align__(16) float At[32][PAD];
    __shared__ __align__(16) float Wks[32][PAD];
    __shared__ __align__(16) float Wvs[32][PAD];

    const int tid = threadIdx.x;
    const int ty = tid >> 4, tx = tid & 15;
    const size_t row0 = (size_t)blockIdx.x * 64;

    u64 ak2[2][4], av2[2][4];
#pragma unroll
    for (int i = 0; i < 2; i++)
#pragma unroll
        for (int j = 0; j < 4; j++) { ak2[i][j] = 0ull; av2[i][j] = 0ull; }

    for (int k0 = 0; k0 < DIN_; k0 += 32) {
#pragma unroll
        for (int i = tid; i < 64 * 32; i += 256) {
            int r = i >> 5, c = i & 31;
            At[c][r] = A[(row0 + r) * DIN_ + k0 + c];
        }
#pragma unroll
        for (int i = tid; i < 32 * 64; i += 256) {
            int r = i >> 6, c = i & 63;
            Wks[r][c] = Wk[(k0 + r) * DO_ + c];
            Wvs[r][c] = Wv[(k0 + r) * DO_ + c];
        }
        __syncthreads();
#pragma unroll 8
        for (int kk = 0; kk < 32; kk++) {
            ulonglong2 a2 = *(const ulonglong2*)&At[kk][4 * ty];
            float4 bk = *(const float4*)&Wks[kk][4 * tx];
            float4 bv = *(const float4*)&Wvs[kk][4 * tx];
            u64 ap[2] = {a2.x, a2.y};
            u64 bkp[4] = {pk2(bk.x, bk.x), pk2(bk.y, bk.y),
                          pk2(bk.z, bk.z), pk2(bk.w, bk.w)};
            u64 bvp[4] = {pk2(bv.x, bv.x), pk2(bv.y, bv.y),
                          pk2(bv.z, bv.z), pk2(bv.w, bv.w)};
#pragma unroll
            for (int i = 0; i < 2; i++)
#pragma unroll
                for (int j = 0; j < 4; j++) {
                    ak2[i][j] = ffma2(ap[i], bkp[j], ak2[i][j]);
                    av2[i][j] = ffma2(ap[i], bvp[j], av2[i][j]);
                }
        }
        __syncthreads();
    }
#pragma unroll
    for (int i = 0; i < 2; i++)
#pragma unroll
        for (int j = 0; j < 4; j++) {
            float klo, khi, vlo, vhi;
            upk2(ak2[i][j], klo, khi);
            upk2(av2[i][j], vlo, vhi);
            size_t r0 = row0 + 4 * ty + 2 * i;
            int c = 4 * tx + j;
            __nv_bfloat16 h, l;
            split_bf16(klo, h, l); okh[r0 * DO_ + c] = h; okl[r0 * DO_ + c] = l;
            split_bf16(khi, h, l); okh[(r0 + 1) * DO_ + c] = h; okl[(r0 + 1) * DO_ + c] = l;
            size_t b0 = r0 >> 11, j0 = r0 & 2047;
            split_bf16(vlo, h, l);
            ovh[(b0 * DO_ + c) * LK_ + j0] = h; ovl[(b0 * DO_ + c) * LK_ + j0] = l;
            size_t b1 = (r0 + 1) >> 11, j1 = (r0 + 1) & 2047;
            split_bf16(vhi, h, l);
            ovh[(b1 * DO_ + c) * LK_ + j1] = h; ovl[(b1 * DO_ + c) * LK_ + j1] = l;
        }
}

// ---------------------------------------------------------------------------
// mma.sync flash attention: 64 q-rows/CTA, 4 warps (warp = m16 x n64).
// Split-precision bf16 (hh + hl + lh), fp32 accum, no max-subtraction.
// ---------------------------------------------------------------------------
#define RSTRIDE 144              // 72 bf16 per smem row (64 data + 8 pad)
#define TILE_B  (64 * RSTRIDE)   // 9216 bytes per 64x64 bf16 tile
// smem byte offsets
#define O_QH  0
#define O_QL  (TILE_B)
#define O_KH  (2 * TILE_B)
#define O_KL  (3 * TILE_B)
#define O_VH  (4 * TILE_B)
#define O_VL  (5 * TILE_B)
#define SM_BYTES (6 * TILE_B)    // 55296

__global__ __launch_bounds__(128) void attn_mma_kernel(
    const __nv_bfloat16* __restrict__ qh, const __nv_bfloat16* __restrict__ ql,
    const __nv_bfloat16* __restrict__ kh, const __nv_bfloat16* __restrict__ kl,
    const __nv_bfloat16* __restrict__ vth, const __nv_bfloat16* __restrict__ vtl,
    float* __restrict__ out)
{
    extern __shared__ __align__(16) char sm[];
    const uint32_t sb = smem_u32(sm);

    const int tid = threadIdx.x;
    const int w = tid >> 5;
    const int lane = tid & 31;
    const int b = blockIdx.y;
    const size_t q0 = (size_t)blockIdx.x * 64;

    // ---- load Q tiles (hi, lo): 2 x 64 rows x 8 x 16B chunks ----
#pragma unroll
    for (int i = tid; i < 1024; i += 128) {
        int t = i >> 9, r = (i >> 3) & 63, c = i & 7;
        const __nv_bfloat16* src = (t ? ql : qh) + ((size_t)b * LQ_ + q0 + r) * DO_ + c * 8;
        *(uint4*)(sm + (t ? O_QL : O_QH) + r * RSTRIDE + c * 16) = *(const uint4*)src;
    }
    __syncthreads();

    // ---- Q fragments (held for whole kernel) ----
    // A-frag addr: row = 16w + (lane&7) + 8*((lane>>3)&1), col = 16g + 8*(lane>>4)
    uint32_t qfh[4][4], qfl[4][4];
    {
        int arow = 16 * w + (lane & 7) + 8 * ((lane >> 3) & 1);
        int acol = 8 * (lane >> 4);
        uint32_t base = (uint32_t)(arow * RSTRIDE + acol * 2);
#pragma unroll
        for (int g = 0; g < 4; g++) {
            ldsm_x4(qfh[g], sb + O_QH + base + 32 * g);
            ldsm_x4(qfl[g], sb + O_QL + base + 32 * g);
        }
    }

    // B-frag per-thread offset: row = (lane&7), col = 8*(lane>>3)
    const uint32_t boff = (uint32_t)((lane & 7) * RSTRIDE + (lane >> 3) * 16);

    float oacc[8][4];
#pragma unroll
    for (int j = 0; j < 8; j++)
#pragma unroll
        for (int c = 0; c < 4; c++) oacc[j][c] = 0.f;
    float lsum0 = 0.f, lsum1 = 0.f;

    for (int it = 0; it < LK_ / 64; it++) {
        const int kt = it * 64;
        // ---- load K (hi,lo) + Vt (hi,lo): 4 x 512 chunks ----
#pragma unroll
        for (int i = tid; i < 2048; i += 128) {
            int t = i >> 9, r = (i >> 3) & 63, c = i & 7;
            const __nv_bfloat16* src;
            int dst;
            if (t == 0)      { src = kh  + ((size_t)b * LK_ + kt + r) * DO_ + c * 8; dst = O_KH; }
            else if (t == 1) { src = kl  + ((size_t)b * LK_ + kt + r) * DO_ + c * 8; dst = O_KL; }
            else if (t == 2) { src = vth + ((size_t)b * DO_ + r) * LK_ + kt + c * 8; dst = O_VH; }
            else             { src = vtl + ((size_t)b * DO_ + r) * LK_ + kt + c * 8; dst = O_VL; }
            *(uint4*)(sm + dst + r * RSTRIDE + c * 16) = *(const uint4*)src;
        }
        __syncthreads();

        // ---- S = (Qh+Ql)(Kh+Kl)^T : warp m16 x n64 ----
        float sacc[8][4];
#pragma unroll
        for (int j = 0; j < 8; j++)
#pragma unroll
            for (int c = 0; c < 4; c++) sacc[j][c] = 0.f;

#pragma unroll
        for (int j = 0; j < 8; j++) {
            uint32_t bh[8], bl[8];
            uint32_t kbase = sb + O_KH + j * (8 * RSTRIDE) + boff;
            ldsm_x4(bh, kbase);
            ldsm_x4(bh + 4, kbase + 64);
            uint32_t lbase = sb + O_KL + j * (8 * RSTRIDE) + boff;
            ldsm_x4(bl, lbase);
            ldsm_x4(bl + 4, lbase + 64);
#pragma unroll
            for (int s = 0; s < 4; s++) {
                mma16816(sacc[j], qfh[s], bh[2 * s], bh[2 * s + 1]);
                mma16816(sacc[j], qfh[s], bl[2 * s], bl[2 * s + 1]);
                mma16816(sacc[j], qfl[s], bh[2 * s], bh[2 * s + 1]);
            }
        }

        // ---- exp (no max-sub), row sums, build P fragments (hi/lo) ----
        uint32_t pfh[4][4], pfl[4][4];
#pragma unroll
        for (int g = 0; g < 4; g++) {
            float p[8];
            p[0] = __expf(sacc[2 * g][0]);     p[1] = __expf(sacc[2 * g][1]);
            p[2] = __expf(sacc[2 * g][2]);     p[3] = __expf(sacc[2 * g][3]);
            p[4] = __expf(sacc[2 * g + 1][0]); p[5] = __expf(sacc[2 * g + 1][1]);
            p[6] = __expf(sacc[2 * g + 1][2]); p[7] = __expf(sacc[2 * g + 1][3]);
            lsum0 += (p[0] + p[1]) + (p[4] + p[5]);
            lsum1 += (p[2] + p[3]) + (p[6] + p[7]);
#pragma unroll
            for (int q = 0; q < 4; q++) {
                float e0 = p[2 * q], e1 = p[2 * q + 1];
                __nv_bfloat16 h0 = __float2bfloat16(e0);
                __nv_bfloat16 h1 = __float2bfloat16(e1);
                __nv_bfloat162 hp = __halves2bfloat162(h0, h1);
                __nv_bfloat162 lp = __halves2bfloat162(
                    __float2bfloat16(e0 - __bfloat162float(h0)),
                    __float2bfloat16(e1 - __bfloat162float(h1)));
                pfh[g][q] = *(uint32_t*)&hp;
                pfl[g][q] = *(uint32_t*)&lp;
            }
        }

        // ---- O += (Ph+Pl)(Vh+Vl) : B from Vt tiles ----
#pragma unroll
        for (int j = 0; j < 8; j++) {
            uint32_t vh[8], vl[8];
            uint32_t hbase = sb + O_VH + j * (8 * RSTRIDE) + boff;
            ldsm_x4(vh, hbase);
            ldsm_x4(vh + 4, hbase + 64);
            uint32_t lbase = sb + O_VL + j * (8 * RSTRIDE) + boff;
            ldsm_x4(vl, lbase);
            ldsm_x4(vl + 4, lbase + 64);
#pragma unroll
            for (int s = 0; s < 4; s++) {
                mma16816(oacc[j], pfh[s], vh[2 * s], vh[2 * s + 1]);
                mma16816(oacc[j], pfh[s], vl[2 * s], vl[2 * s + 1]);
                mma16816(oacc[j], pfl[s], vh[2 * s], vh[2 * s + 1]);
            }
        }
        __syncthreads();   // all warps done reading tiles before next overwrite
    }

    // ---- finalize: reduce l across quad, normalize, store ----
    lsum0 += __shfl_xor_sync(0xffffffffu, lsum0, 1);
    lsum0 += __shfl_xor_sync(0xffffffffu, lsum0, 2);
    lsum1 += __shfl_xor_sync(0xffffffffu, lsum1, 1);
    lsum1 += __shfl_xor_sync(0xffffffffu, lsum1, 2);
    float inv0 = 1.0f / lsum0;
    float inv1 = 1.0f / lsum1;

    int row = 16 * w + (lane >> 2);
    float* ob = out + ((size_t)b * LQ_ + q0 + row) * DO_ + (lane & 3) * 2;
#pragma unroll
    for (int j = 0; j < 8; j++) {
        *(float2*)(ob + 8 * j) = make_float2(oacc[j][0] * inv0, oacc[j][1] * inv0);
        *(float2*)(ob + 8 * j + 8 * DO_) = make_float2(oacc[j][2] * inv1, oacc[j][3] * inv1);
    }
}

// ---------------------------------------------------------------------------
extern "C" void kernel_launch(void* const* d_in, const int* in_sizes, int n_in,
                              void* d_out, int out_size)
{
    const float* query = (const float*)d_in[0];
    const float* key   = (const float*)d_in[1];
    const float* Wq    = (const float*)d_in[2];
    const float* Wk    = (const float*)d_in[3];
    const float* Wv    = (const float*)d_in[4];
    float* out = (float*)d_out;

    __nv_bfloat16 *qh, *ql, *khp, *klp, *vth, *vtl;
    cudaGetSymbolAddress((void**)&qh, g_qh);
    cudaGetSymbolAddress((void**)&ql, g_ql);
    cudaGetSymbolAddress((void**)&khp, g_kh);
    cudaGetSymbolAddress((void**)&klp, g_kl);
    cudaGetSymbolAddress((void**)&vth, g_vth);
    cudaGetSymbolAddress((void**)&vtl, g_vtl);

    const int projBlocks = (B_ * LQ_) / 64;   // 256
    proj_q_kernel<<<projBlocks, 256>>>(query, Wq, qh, ql);
    proj_kv_kernel<<<projBlocks, 256>>>(key, Wk, Wv, khp, klp, vth, vtl);

    cudaFuncSetAttribute(attn_mma_kernel,
                         cudaFuncAttributeMaxDynamicSharedMemorySize, SM_BYTES);
    dim3 grid(LQ_ / 64, B_);   // (32, 8) = 256 CTAs
    attn_mma_kernel<<<grid, 128, SM_BYTES>>>(qh, ql, khp, klp, vth, vtl, out);
}

// round 8
// speedup vs baseline: 2.4808x; 1.1719x over previous
#include <cuda_runtime.h>
#include <cuda_bf16.h>
#include <math.h>
#include <stdint.h>

// Problem constants
#define B_   8
#define LQ_  2048
#define LK_  2048
#define DIN_ 128
#define DO_  64

#define PAD 68
typedef unsigned long long u64;

// ---- f32x2 helpers (projection) -------------------------------------------
__device__ __forceinline__ u64 pk2(float lo, float hi) {
    u64 r; asm("mov.b64 %0, {%1, %2};" : "=l"(r) : "f"(lo), "f"(hi)); return r;
}
__device__ __forceinline__ void upk2(u64 v, float& lo, float& hi) {
    asm("mov.b64 {%0, %1}, %2;" : "=f"(lo), "=f"(hi) : "l"(v));
}
__device__ __forceinline__ u64 ffma2(u64 a, u64 b, u64 c) {
    u64 d; asm("fma.rn.f32x2 %0, %1, %2, %3;" : "=l"(d) : "l"(a), "l"(b), "l"(c));
    return d;
}

// ---- tensor-core + async primitives (baseline PTX, OK for plain sm_103) ---
__device__ __forceinline__ void ldsm_x4(uint32_t* r, uint32_t addr) {
    asm volatile("ldmatrix.sync.aligned.m8n8.x4.shared.b16 {%0,%1,%2,%3}, [%4];"
        : "=r"(r[0]), "=r"(r[1]), "=r"(r[2]), "=r"(r[3]) : "r"(addr));
}
__device__ __forceinline__ void mma16816(float* d, const uint32_t* a,
                                         uint32_t b0, uint32_t b1) {
    asm volatile(
        "mma.sync.aligned.m16n8k16.row.col.f32.bf16.bf16.f32 "
        "{%0,%1,%2,%3}, {%4,%5,%6,%7}, {%8,%9}, {%0,%1,%2,%3};"
        : "+f"(d[0]), "+f"(d[1]), "+f"(d[2]), "+f"(d[3])
        : "r"(a[0]), "r"(a[1]), "r"(a[2]), "r"(a[3]), "r"(b0), "r"(b1));
}
__device__ __forceinline__ uint32_t smem_u32(const void* p) {
    uint32_t a;
    asm("{ .reg .u64 t; cvta.to.shared.u64 t, %1; cvt.u32.u64 %0, t; }"
        : "=r"(a) : "l"(p));
    return a;
}
__device__ __forceinline__ void cp_async16(uint32_t dst, const void* src) {
    asm volatile("cp.async.ca.shared.global [%0], [%1], 16;"
                 :: "r"(dst), "l"(src) : "memory");
}
#define CP_COMMIT()   asm volatile("cp.async.commit_group;" ::: "memory")
#define CP_WAIT_ALL() asm volatile("cp.async.wait_group 0;" ::: "memory")

// ---- Scratch: bf16 hi/lo splits -------------------------------------------
__device__ __nv_bfloat16 g_qh[B_ * LQ_ * DO_];
__device__ __nv_bfloat16 g_ql[B_ * LQ_ * DO_];
__device__ __nv_bfloat16 g_kh[B_ * LK_ * DO_];
__device__ __nv_bfloat16 g_kl[B_ * LK_ * DO_];
__device__ __nv_bfloat16 g_vth[B_ * DO_ * LK_];   // [b][dim][key]
__device__ __nv_bfloat16 g_vtl[B_ * DO_ * LK_];

__device__ __forceinline__ void split_bf16(float x, __nv_bfloat16& h, __nv_bfloat16& l) {
    h = __float2bfloat16(x);
    l = __float2bfloat16(x - __bfloat162float(h));
}

// ---------------------------------------------------------------------------
// Merged projections: grid 512. blocks [0,256) -> Q path, [256,512) -> K+V.
// ---------------------------------------------------------------------------
__global__ __launch_bounds__(256) void proj_all_kernel(
    const float* __restrict__ query, const float* __restrict__ key,
    const float* __restrict__ Wq, const float* __restrict__ Wk,
    const float* __restrict__ Wv,
    __nv_bfloat16* __restrict__ oqh, __nv_bfloat16* __restrict__ oql,
    __nv_bfloat16* __restrict__ okh, __nv_bfloat16* __restrict__ okl,
    __nv_bfloat16* __restrict__ ovh, __nv_bfloat16* __restrict__ ovl)
{
    __shared__ __align__(16) float At[32][PAD];
    __shared__ __align__(16) float W1s[32][PAD];
    __shared__ __align__(16) float W2s[32][PAD];

    const int tid = threadIdx.x;
    const int ty = tid >> 4, tx = tid & 15;
    const bool qpath = blockIdx.x < 256;
    const size_t row0 = (size_t)(qpath ? blockIdx.x : blockIdx.x - 256) * 64;
    const float* A = qpath ? query : key;

    if (qpath) {
        u64 acc2[2][4];
#pragma unroll
        for (int i = 0; i < 2; i++)
#pragma unroll
            for (int j = 0; j < 4; j++) acc2[i][j] = 0ull;

        for (int k0 = 0; k0 < DIN_; k0 += 32) {
#pragma unroll
            for (int i = tid; i < 64 * 32; i += 256) {
                int r = i >> 5, c = i & 31;
                At[c][r] = A[(row0 + r) * DIN_ + k0 + c];
            }
#pragma unroll
            for (int i = tid; i < 32 * 64; i += 256) {
                int r = i >> 6, c = i & 63;
                W1s[r][c] = Wq[(k0 + r) * DO_ + c];
            }
            __syncthreads();
#pragma unroll 8
            for (int kk = 0; kk < 32; kk++) {
                ulonglong2 a2 = *(const ulonglong2*)&At[kk][4 * ty];
                float4 b4 = *(const float4*)&W1s[kk][4 * tx];
                u64 ap[2] = {a2.x, a2.y};
                u64 bp[4] = {pk2(b4.x, b4.x), pk2(b4.y, b4.y),
                             pk2(b4.z, b4.z), pk2(b4.w, b4.w)};
#pragma unroll
                for (int i = 0; i < 2; i++)
#pragma unroll
                    for (int j = 0; j < 4; j++)
                        acc2[i][j] = ffma2(ap[i], bp[j], acc2[i][j]);
            }
            __syncthreads();
        }
#pragma unroll
        for (int i = 0; i < 2; i++)
#pragma unroll
            for (int j = 0; j < 4; j++) {
                float lo, hi;
                upk2(acc2[i][j], lo, hi);
                size_t r0 = row0 + 4 * ty + 2 * i;
                int c = 4 * tx + j;
                __nv_bfloat16 h, l;
                split_bf16(lo, h, l); oqh[r0 * DO_ + c] = h; oql[r0 * DO_ + c] = l;
                split_bf16(hi, h, l); oqh[(r0 + 1) * DO_ + c] = h; oql[(r0 + 1) * DO_ + c] = l;
            }
    } else {
        u64 ak2[2][4], av2[2][4];
#pragma unroll
        for (int i = 0; i < 2; i++)
#pragma unroll
            for (int j = 0; j < 4; j++) { ak2[i][j] = 0ull; av2[i][j] = 0ull; }

        for (int k0 = 0; k0 < DIN_; k0 += 32) {
#pragma unroll
            for (int i = tid; i < 64 * 32; i += 256) {
                int r = i >> 5, c = i & 31;
                At[c][r] = A[(row0 + r) * DIN_ + k0 + c];
            }
#pragma unroll
            for (int i = tid; i < 32 * 64; i += 256) {
                int r = i >> 6, c = i & 63;
                W1s[r][c] = Wk[(k0 + r) * DO_ + c];
                W2s[r][c] = Wv[(k0 + r) * DO_ + c];
            }
            __syncthreads();
#pragma unroll 8
            for (int kk = 0; kk < 32; kk++) {
                ulonglong2 a2 = *(const ulonglong2*)&At[kk][4 * ty];
                float4 bk = *(const float4*)&W1s[kk][4 * tx];
                float4 bv = *(const float4*)&W2s[kk][4 * tx];
                u64 ap[2] = {a2.x, a2.y};
                u64 bkp[4] = {pk2(bk.x, bk.x), pk2(bk.y, bk.y),
                              pk2(bk.z, bk.z), pk2(bk.w, bk.w)};
                u64 bvp[4] = {pk2(bv.x, bv.x), pk2(bv.y, bv.y),
                              pk2(bv.z, bv.z), pk2(bv.w, bv.w)};
#pragma unroll
                for (int i = 0; i < 2; i++)
#pragma unroll
                    for (int j = 0; j < 4; j++) {
                        ak2[i][j] = ffma2(ap[i], bkp[j], ak2[i][j]);
                        av2[i][j] = ffma2(ap[i], bvp[j], av2[i][j]);
                    }
            }
            __syncthreads();
        }
#pragma unroll
        for (int i = 0; i < 2; i++)
#pragma unroll
            for (int j = 0; j < 4; j++) {
                float klo, khi, vlo, vhi;
                upk2(ak2[i][j], klo, khi);
                upk2(av2[i][j], vlo, vhi);
                size_t r0 = row0 + 4 * ty + 2 * i;
                int c = 4 * tx + j;
                __nv_bfloat16 h, l;
                split_bf16(klo, h, l); okh[r0 * DO_ + c] = h; okl[r0 * DO_ + c] = l;
                split_bf16(khi, h, l); okh[(r0 + 1) * DO_ + c] = h; okl[(r0 + 1) * DO_ + c] = l;
                size_t b0 = r0 >> 11, j0 = r0 & 2047;
                split_bf16(vlo, h, l);
                ovh[(b0 * DO_ + c) * LK_ + j0] = h; ovl[(b0 * DO_ + c) * LK_ + j0] = l;
                size_t b1 = (r0 + 1) >> 11, j1 = (r0 + 1) & 2047;
                split_bf16(vhi, h, l);
                ovh[(b1 * DO_ + c) * LK_ + j1] = h; ovl[(b1 * DO_ + c) * LK_ + j1] = l;
            }
    }
}

// ---------------------------------------------------------------------------
// mma.sync flash attention. BQ=128/CTA, 4 warps, warp = m32 x n64.
// Double-buffered K/V via cp.async. Split-precision bf16 (hh+hl+lh).
// ---------------------------------------------------------------------------
#define RSTRIDE 144
#define TILE_B  (64 * RSTRIDE)      // 9216
#define QTILE_B (128 * RSTRIDE)     // 18432
#define O_QH  0
#define O_QL  QTILE_B
#define O_KV  (2 * QTILE_B)         // 36864
#define KVBUF (4 * TILE_B)          // 36864 (KH, KL, VH, VL)
#define SM_BYTES (O_KV + 2 * KVBUF) // 110592

__device__ __forceinline__ void kv_load(
    uint32_t dstbase, int tid, int b, int kt,
    const __nv_bfloat16* __restrict__ kh, const __nv_bfloat16* __restrict__ kl,
    const __nv_bfloat16* __restrict__ vth, const __nv_bfloat16* __restrict__ vtl)
{
#pragma unroll
    for (int n = 0; n < 16; n++) {
        int i = tid + n * 128;
        int t = i >> 9, r = (i >> 3) & 63, c = i & 7;
        const __nv_bfloat16* src;
        if (t == 0)      src = kh  + ((size_t)b * LK_ + kt + r) * DO_ + c * 8;
        else if (t == 1) src = kl  + ((size_t)b * LK_ + kt + r) * DO_ + c * 8;
        else if (t == 2) src = vth + ((size_t)b * DO_ + r) * LK_ + kt + c * 8;
        else             src = vtl + ((size_t)b * DO_ + r) * LK_ + kt + c * 8;
        cp_async16(dstbase + t * TILE_B + r * RSTRIDE + c * 16, src);
    }
}

__global__ __launch_bounds__(128) void attn_mma_kernel(
    const __nv_bfloat16* __restrict__ qh, const __nv_bfloat16* __restrict__ ql,
    const __nv_bfloat16* __restrict__ kh, const __nv_bfloat16* __restrict__ kl,
    const __nv_bfloat16* __restrict__ vth, const __nv_bfloat16* __restrict__ vtl,
    float* __restrict__ out)
{
    extern __shared__ __align__(16) char sm[];
    const uint32_t sb = smem_u32(sm);

    const int tid = threadIdx.x;
    const int w = tid >> 5;
    const int lane = tid & 31;
    const int b = blockIdx.y;
    const size_t q0 = (size_t)blockIdx.x * 128;

    // ---- prefetch Q (hi, lo) + first KV tile set ----
#pragma unroll
    for (int n = 0; n < 16; n++) {
        int i = tid + n * 128;
        int t = i >> 10, r = (i >> 3) & 127, c = i & 7;
        const __nv_bfloat16* src =
            (t ? ql : qh) + ((size_t)b * LQ_ + q0 + r) * DO_ + c * 8;
        cp_async16(sb + (t ? O_QL : O_QH) + r * RSTRIDE + c * 16, src);
    }
    kv_load(sb + O_KV, tid, b, 0, kh, kl, vth, vtl);
    CP_COMMIT();
    CP_WAIT_ALL();
    __syncthreads();

    // ---- Q fragments: warp = rows 32w..32w+31 (two m16 blocks) ----
    uint32_t qfh[2][4][4], qfl[2][4][4];
#pragma unroll
    for (int mi = 0; mi < 2; mi++) {
        int arow = 32 * w + 16 * mi + (lane & 7) + 8 * ((lane >> 3) & 1);
        int acol = 8 * (lane >> 4);
        uint32_t base = (uint32_t)(arow * RSTRIDE + acol * 2);
#pragma unroll
        for (int g = 0; g < 4; g++) {
            ldsm_x4(qfh[mi][g], sb + O_QH + base + 32 * g);
            ldsm_x4(qfl[mi][g], sb + O_QL + base + 32 * g);
        }
    }

    const uint32_t boff = (uint32_t)((lane & 7) * RSTRIDE + (lane >> 3) * 16);

    float oacc[2][8][4];
#pragma unroll
    for (int mi = 0; mi < 2; mi++)
#pragma unroll
        for (int j = 0; j < 8; j++)
#pragma unroll
            for (int c = 0; c < 4; c++) oacc[mi][j][c] = 0.f;
    float lsum[2][2] = {{0.f, 0.f}, {0.f, 0.f}};

    for (int it = 0; it < LK_ / 64; it++) {
        const uint32_t kvb = sb + O_KV + (uint32_t)(it & 1) * KVBUF;
        if (it + 1 < LK_ / 64) {
            kv_load(sb + O_KV + (uint32_t)((it + 1) & 1) * KVBUF,
                    tid, b, (it + 1) * 64, kh, kl, vth, vtl);
            CP_COMMIT();
        }

#pragma unroll 1
        for (int half = 0; half < 2; half++) {
            // ---- S = (Qh+Ql)(Kh+Kl)^T for 32-key half: m32 x n32 ----
            float sacc[2][4][4];
#pragma unroll
            for (int mi = 0; mi < 2; mi++)
#pragma unroll
                for (int jj = 0; jj < 4; jj++)
#pragma unroll
                    for (int c = 0; c < 4; c++) sacc[mi][jj][c] = 0.f;

#pragma unroll
            for (int jj = 0; jj < 4; jj++) {
                int j = 4 * half + jj;   // n8 block = keys 8j..8j+7
                uint32_t bh[8], bl[8];
                uint32_t kb = kvb + j * (8 * RSTRIDE) + boff;
                ldsm_x4(bh, kb);
                ldsm_x4(bh + 4, kb + 64);
                uint32_t lb = kvb + TILE_B + j * (8 * RSTRIDE) + boff;
                ldsm_x4(bl, lb);
                ldsm_x4(bl + 4, lb + 64);
#pragma unroll
                for (int mi = 0; mi < 2; mi++)
#pragma unroll
                    for (int s = 0; s < 4; s++) {
                        mma16816(sacc[mi][jj], qfh[mi][s], bh[2 * s], bh[2 * s + 1]);
                        mma16816(sacc[mi][jj], qfh[mi][s], bl[2 * s], bl[2 * s + 1]);
                        mma16816(sacc[mi][jj], qfl[mi][s], bh[2 * s], bh[2 * s + 1]);
                    }
            }

            // ---- exp (no max-sub), row sums, P fragments for k32 ----
            uint32_t pfh[2][2][4], pfl[2][2][4];
#pragma unroll
            for (int mi = 0; mi < 2; mi++)
#pragma unroll
                for (int sg = 0; sg < 2; sg++) {
                    float p[8];
                    p[0] = __expf(sacc[mi][2 * sg][0]);
                    p[1] = __expf(sacc[mi][2 * sg][1]);
                    p[2] = __expf(sacc[mi][2 * sg][2]);
                    p[3] = __expf(sacc[mi][2 * sg][3]);
                    p[4] = __expf(sacc[mi][2 * sg + 1][0]);
                    p[5] = __expf(sacc[mi][2 * sg + 1][1]);
                    p[6] = __expf(sacc[mi][2 * sg + 1][2]);
                    p[7] = __expf(sacc[mi][2 * sg + 1][3]);
                    lsum[mi][0] += (p[0] + p[1]) + (p[4] + p[5]);
                    lsum[mi][1] += (p[2] + p[3]) + (p[6] + p[7]);
#pragma unroll
                    for (int q = 0; q < 4; q++) {
                        float e0 = p[2 * q], e1 = p[2 * q + 1];
                        __nv_bfloat16 h0 = __float2bfloat16(e0);
                        __nv_bfloat16 h1 = __float2bfloat16(e1);
                        __nv_bfloat162 hp = __halves2bfloat162(h0, h1);
                        __nv_bfloat162 lp = __halves2bfloat162(
                            __float2bfloat16(e0 - __bfloat162float(h0)),
                            __float2bfloat16(e1 - __bfloat162float(h1)));
                        pfh[mi][sg][q] = *(uint32_t*)&hp;
                        pfl[mi][sg][q] = *(uint32_t*)&lp;
                    }
                }

            // ---- O += (Ph+Pl)(Vh+Vl) for this 32-key half ----
#pragma unroll
            for (int j = 0; j < 8; j++) {   // Dout n8 block
                uint32_t vh[4], vl[4];
                uint32_t vb = kvb + 2 * TILE_B + j * (8 * RSTRIDE) + half * 64 + boff;
                ldsm_x4(vh, vb);
                ldsm_x4(vl, vb + TILE_B);
#pragma unroll
                for (int mi = 0; mi < 2; mi++)
#pragma unroll
                    for (int sg = 0; sg < 2; sg++) {
                        mma16816(oacc[mi][j], pfh[mi][sg], vh[2 * sg], vh[2 * sg + 1]);
                        mma16816(oacc[mi][j], pfh[mi][sg], vl[2 * sg], vl[2 * sg + 1]);
                        mma16816(oacc[mi][j], pfl[mi][sg], vh[2 * sg], vh[2 * sg + 1]);
                    }
            }
        }

        CP_WAIT_ALL();
        __syncthreads();
    }

    // ---- finalize ----
#pragma unroll
    for (int mi = 0; mi < 2; mi++) {
        float l0 = lsum[mi][0], l1 = lsum[mi][1];
        l0 += __shfl_xor_sync(0xffffffffu, l0, 1);
        l0 += __shfl_xor_sync(0xffffffffu, l0, 2);
        l1 += __shfl_xor_sync(0xffffffffu, l1, 1);
        l1 += __shfl_xor_sync(0xffffffffu, l1, 2);
        float inv0 = 1.0f / l0;
        float inv1 = 1.0f / l1;

        int row = 32 * w + 16 * mi + (lane >> 2);
        float* ob = out + ((size_t)b * LQ_ + q0 + row) * DO_ + (lane & 3) * 2;
#pragma unroll
        for (int j = 0; j < 8; j++) {
            *(float2*)(ob + 8 * j) =
                make_float2(oacc[mi][j][0] * inv0, oacc[mi][j][1] * inv0);
            *(float2*)(ob + 8 * j + 8 * DO_) =
                make_float2(oacc[mi][j][2] * inv1, oacc[mi][j][3] * inv1);
        }
    }
}

// ---------------------------------------------------------------------------
extern "C" void kernel_launch(void* const* d_in, const int* in_sizes, int n_in,
                              void* d_out, int out_size)
{
    const float* query = (const float*)d_in[0];
    const float* key   = (const float*)d_in[1];
    const float* Wq    = (const float*)d_in[2];
    const float* Wk    = (const float*)d_in[3];
    const float* Wv    = (const float*)d_in[4];
    float* out = (float*)d_out;

    __nv_bfloat16 *qh, *ql, *khp, *klp, *vth, *vtl;
    cudaGetSymbolAddress((void**)&qh, g_qh);
    cudaGetSymbolAddress((void**)&ql, g_ql);
    cudaGetSymbolAddress((void**)&khp, g_kh);
    cudaGetSymbolAddress((void**)&klp, g_kl);
    cudaGetSymbolAddress((void**)&vth, g_vth);
    cudaGetSymbolAddress((void**)&vtl, g_vtl);

    proj_all_kernel<<<512, 256>>>(query, key, Wq, Wk, Wv,
                                  qh, ql, khp, klp, vth, vtl);

    cudaFuncSetAttribute(attn_mma_kernel,
                         cudaFuncAttributeMaxDynamicSharedMemorySize, SM_BYTES);
    dim3 grid(LQ_ / 128, B_);   // (16, 8) = 128 CTAs, one wave
    attn_mma_kernel<<<grid, 128, SM_BYTES>>>(qh, ql, khp, klp, vth, vtl, out);
}

// round 9
// speedup vs baseline: 2.5984x; 1.0474x over previous
#include <cuda_runtime.h>
#include <cuda_bf16.h>
#include <math.h>
#include <stdint.h>

// Problem constants
#define B_   8
#define LQ_  2048
#define LK_  2048
#define DIN_ 128
#define DO_  64
#define NROW (B_ * LQ_)   // 16384

#define PAD 68
typedef unsigned long long u64;

// ---- f32x2 helpers (projection) -------------------------------------------
__device__ __forceinline__ u64 pk2(float lo, float hi) {
    u64 r; asm("mov.b64 %0, {%1, %2};" : "=l"(r) : "f"(lo), "f"(hi)); return r;
}
__device__ __forceinline__ void upk2(u64 v, float& lo, float& hi) {
    asm("mov.b64 {%0, %1}, %2;" : "=f"(lo), "=f"(hi) : "l"(v));
}
__device__ __forceinline__ u64 ffma2(u64 a, u64 b, u64 c) {
    u64 d; asm("fma.rn.f32x2 %0, %1, %2, %3;" : "=l"(d) : "l"(a), "l"(b), "l"(c));
    return d;
}

// ---- tensor-core + async primitives (baseline PTX, OK for plain sm_103) ---
__device__ __forceinline__ void ldsm_x4(uint32_t* r, uint32_t addr) {
    asm volatile("ldmatrix.sync.aligned.m8n8.x4.shared.b16 {%0,%1,%2,%3}, [%4];"
        : "=r"(r[0]), "=r"(r[1]), "=r"(r[2]), "=r"(r[3]) : "r"(addr));
}
__device__ __forceinline__ void mma16816(float* d, const uint32_t* a,
                                         uint32_t b0, uint32_t b1) {
    asm volatile(
        "mma.sync.aligned.m16n8k16.row.col.f32.bf16.bf16.f32 "
        "{%0,%1,%2,%3}, {%4,%5,%6,%7}, {%8,%9}, {%0,%1,%2,%3};"
        : "+f"(d[0]), "+f"(d[1]), "+f"(d[2]), "+f"(d[3])
        : "r"(a[0]), "r"(a[1]), "r"(a[2]), "r"(a[3]), "r"(b0), "r"(b1));
}
__device__ __forceinline__ uint32_t smem_u32(const void* p) {
    uint32_t a;
    asm("{ .reg .u64 t; cvta.to.shared.u64 t, %1; cvt.u32.u64 %0, t; }"
        : "=r"(a) : "l"(p));
    return a;
}
__device__ __forceinline__ void cp_async16(uint32_t dst, const void* src) {
    asm volatile("cp.async.ca.shared.global [%0], [%1], 16;"
                 :: "r"(dst), "l"(src) : "memory");
}
#define CP_COMMIT()   asm volatile("cp.async.commit_group;" ::: "memory")
#define CP_WAIT_ALL() asm volatile("cp.async.wait_group 0;" ::: "memory")

// ---- Scratch ---------------------------------------------------------------
__device__ __nv_bfloat16 g_qh[NROW * DO_];
__device__ __nv_bfloat16 g_ql[NROW * DO_];
__device__ __nv_bfloat16 g_kh[NROW * DO_];
__device__ __nv_bfloat16 g_kl[NROW * DO_];
__device__ __nv_bfloat16 g_vth[B_ * DO_ * LK_];   // [b][dim][key]
__device__ __nv_bfloat16 g_vtl[B_ * DO_ * LK_];
__device__ float g_po[2 * NROW * DO_];            // partial O per key-split
__device__ float g_pl[2 * NROW];                  // partial l per key-split

__device__ __forceinline__ void split_bf16(float x, __nv_bfloat16& h, __nv_bfloat16& l) {
    h = __float2bfloat16(x);
    l = __float2bfloat16(x - __bfloat162float(h));
}

// ---------------------------------------------------------------------------
// Merged projections: grid 512. blocks [0,256) -> Q path, [256,512) -> K+V.
// ---------------------------------------------------------------------------
__global__ __launch_bounds__(256) void proj_all_kernel(
    const float* __restrict__ query, const float* __restrict__ key,
    const float* __restrict__ Wq, const float* __restrict__ Wk,
    const float* __restrict__ Wv,
    __nv_bfloat16* __restrict__ oqh, __nv_bfloat16* __restrict__ oql,
    __nv_bfloat16* __restrict__ okh, __nv_bfloat16* __restrict__ okl,
    __nv_bfloat16* __restrict__ ovh, __nv_bfloat16* __restrict__ ovl)
{
    __shared__ __align__(16) float At[32][PAD];
    __shared__ __align__(16) float W1s[32][PAD];
    __shared__ __align__(16) float W2s[32][PAD];

    const int tid = threadIdx.x;
    const int ty = tid >> 4, tx = tid & 15;
    const bool qpath = blockIdx.x < 256;
    const size_t row0 = (size_t)(qpath ? blockIdx.x : blockIdx.x - 256) * 64;
    const float* A = qpath ? query : key;

    if (qpath) {
        u64 acc2[2][4];
#pragma unroll
        for (int i = 0; i < 2; i++)
#pragma unroll
            for (int j = 0; j < 4; j++) acc2[i][j] = 0ull;

        for (int k0 = 0; k0 < DIN_; k0 += 32) {
#pragma unroll
            for (int i = tid; i < 64 * 32; i += 256) {
                int r = i >> 5, c = i & 31;
                At[c][r] = A[(row0 + r) * DIN_ + k0 + c];
            }
#pragma unroll
            for (int i = tid; i < 32 * 64; i += 256) {
                int r = i >> 6, c = i & 63;
                W1s[r][c] = Wq[(k0 + r) * DO_ + c];
            }
            __syncthreads();
#pragma unroll 8
            for (int kk = 0; kk < 32; kk++) {
                ulonglong2 a2 = *(const ulonglong2*)&At[kk][4 * ty];
                float4 b4 = *(const float4*)&W1s[kk][4 * tx];
                u64 ap[2] = {a2.x, a2.y};
                u64 bp[4] = {pk2(b4.x, b4.x), pk2(b4.y, b4.y),
                             pk2(b4.z, b4.z), pk2(b4.w, b4.w)};
#pragma unroll
                for (int i = 0; i < 2; i++)
#pragma unroll
                    for (int j = 0; j < 4; j++)
                        acc2[i][j] = ffma2(ap[i], bp[j], acc2[i][j]);
            }
            __syncthreads();
        }
#pragma unroll
        for (int i = 0; i < 2; i++)
#pragma unroll
            for (int j = 0; j < 4; j++) {
                float lo, hi;
                upk2(acc2[i][j], lo, hi);
                size_t r0 = row0 + 4 * ty + 2 * i;
                int c = 4 * tx + j;
                __nv_bfloat16 h, l;
                split_bf16(lo, h, l); oqh[r0 * DO_ + c] = h; oql[r0 * DO_ + c] = l;
                split_bf16(hi, h, l); oqh[(r0 + 1) * DO_ + c] = h; oql[(r0 + 1) * DO_ + c] = l;
            }
    } else {
        u64 ak2[2][4], av2[2][4];
#pragma unroll
        for (int i = 0; i < 2; i++)
#pragma unroll
            for (int j = 0; j < 4; j++) { ak2[i][j] = 0ull; av2[i][j] = 0ull; }

        for (int k0 = 0; k0 < DIN_; k0 += 32) {
#pragma unroll
            for (int i = tid; i < 64 * 32; i += 256) {
                int r = i >> 5, c = i & 31;
                At[c][r] = A[(row0 + r) * DIN_ + k0 + c];
            }
#pragma unroll
            for (int i = tid; i < 32 * 64; i += 256) {
                int r = i >> 6, c = i & 63;
                W1s[r][c] = Wk[(k0 + r) * DO_ + c];
                W2s[r][c] = Wv[(k0 + r) * DO_ + c];
            }
            __syncthreads();
#pragma unroll 8
            for (int kk = 0; kk < 32; kk++) {
                ulonglong2 a2 = *(const ulonglong2*)&At[kk][4 * ty];
                float4 bk = *(const float4*)&W1s[kk][4 * tx];
                float4 bv = *(const float4*)&W2s[kk][4 * tx];
                u64 ap[2] = {a2.x, a2.y};
                u64 bkp[4] = {pk2(bk.x, bk.x), pk2(bk.y, bk.y),
                              pk2(bk.z, bk.z), pk2(bk.w, bk.w)};
                u64 bvp[4] = {pk2(bv.x, bv.x), pk2(bv.y, bv.y),
                              pk2(bv.z, bv.z), pk2(bv.w, bv.w)};
#pragma unroll
                for (int i = 0; i < 2; i++)
#pragma unroll
                    for (int j = 0; j < 4; j++) {
                        ak2[i][j] = ffma2(ap[i], bkp[j], ak2[i][j]);
                        av2[i][j] = ffma2(ap[i], bvp[j], av2[i][j]);
                    }
            }
            __syncthreads();
        }
#pragma unroll
        for (int i = 0; i < 2; i++)
#pragma unroll
            for (int j = 0; j < 4; j++) {
                float klo, khi, vlo, vhi;
                upk2(ak2[i][j], klo, khi);
                upk2(av2[i][j], vlo, vhi);
                size_t r0 = row0 + 4 * ty + 2 * i;
                int c = 4 * tx + j;
                __nv_bfloat16 h, l;
                split_bf16(klo, h, l); okh[r0 * DO_ + c] = h; okl[r0 * DO_ + c] = l;
                split_bf16(khi, h, l); okh[(r0 + 1) * DO_ + c] = h; okl[(r0 + 1) * DO_ + c] = l;
                size_t b0 = r0 >> 11, j0 = r0 & 2047;
                split_bf16(vlo, h, l);
                ovh[(b0 * DO_ + c) * LK_ + j0] = h; ovl[(b0 * DO_ + c) * LK_ + j0] = l;
                size_t b1 = (r0 + 1) >> 11, j1 = (r0 + 1) & 2047;
                split_bf16(vhi, h, l);
                ovh[(b1 * DO_ + c) * LK_ + j1] = h; ovl[(b1 * DO_ + c) * LK_ + j1] = l;
            }
    }
}

// ---------------------------------------------------------------------------
// mma.sync flash attention. BQ=128/CTA, 4 warps (m32 x n64), key-split x2
// (blockIdx.z). Double-buffered cp.async. Writes partial O (unnormalized) + l.
// ---------------------------------------------------------------------------
#define RSTRIDE 144
#define TILE_B  (64 * RSTRIDE)      // 9216
#define QTILE_B (128 * RSTRIDE)     // 18432
#define O_QH  0
#define O_QL  QTILE_B
#define O_KV  (2 * QTILE_B)         // 36864
#define KVBUF (4 * TILE_B)          // 36864 (KH, KL, VH, VL)
#define SM_BYTES (O_KV + 2 * KVBUF) // 110592

__device__ __forceinline__ void kv_load(
    uint32_t dstbase, int tid, int b, int kt,
    const __nv_bfloat16* __restrict__ kh, const __nv_bfloat16* __restrict__ kl,
    const __nv_bfloat16* __restrict__ vth, const __nv_bfloat16* __restrict__ vtl)
{
#pragma unroll
    for (int n = 0; n < 16; n++) {
        int i = tid + n * 128;
        int t = i >> 9, r = (i >> 3) & 63, c = i & 7;
        const __nv_bfloat16* src;
        if (t == 0)      src = kh  + ((size_t)b * LK_ + kt + r) * DO_ + c * 8;
        else if (t == 1) src = kl  + ((size_t)b * LK_ + kt + r) * DO_ + c * 8;
        else if (t == 2) src = vth + ((size_t)b * DO_ + r) * LK_ + kt + c * 8;
        else             src = vtl + ((size_t)b * DO_ + r) * LK_ + kt + c * 8;
        cp_async16(dstbase + t * TILE_B + r * RSTRIDE + c * 16, src);
    }
}

__global__ __launch_bounds__(128, 2) void attn_mma_kernel(
    const __nv_bfloat16* __restrict__ qh, const __nv_bfloat16* __restrict__ ql,
    const __nv_bfloat16* __restrict__ kh, const __nv_bfloat16* __restrict__ kl,
    const __nv_bfloat16* __restrict__ vth, const __nv_bfloat16* __restrict__ vtl,
    float* __restrict__ po, float* __restrict__ pl)
{
    extern __shared__ __align__(16) char sm[];
    const uint32_t sb = smem_u32(sm);

    const int tid = threadIdx.x;
    const int w = tid >> 5;
    const int lane = tid & 31;
    const int b = blockIdx.y;
    const int ks = blockIdx.z;            // key split: 0 or 1
    const int it0 = ks * (LK_ / 128);     // 16 tiles of 64 keys each
    const int it1 = it0 + (LK_ / 128);
    const size_t q0 = (size_t)blockIdx.x * 128;

    // ---- prefetch Q (hi, lo) + first KV tile set ----
#pragma unroll
    for (int n = 0; n < 16; n++) {
        int i = tid + n * 128;
        int t = i >> 10, r = (i >> 3) & 127, c = i & 7;
        const __nv_bfloat16* src =
            (t ? ql : qh) + ((size_t)b * LQ_ + q0 + r) * DO_ + c * 8;
        cp_async16(sb + (t ? O_QL : O_QH) + r * RSTRIDE + c * 16, src);
    }
    kv_load(sb + O_KV, tid, b, it0 * 64, kh, kl, vth, vtl);
    CP_COMMIT();
    CP_WAIT_ALL();
    __syncthreads();

    // ---- Q fragments: warp = rows 32w..32w+31 (two m16 blocks) ----
    uint32_t qfh[2][4][4], qfl[2][4][4];
#pragma unroll
    for (int mi = 0; mi < 2; mi++) {
        int arow = 32 * w + 16 * mi + (lane & 7) + 8 * ((lane >> 3) & 1);
        int acol = 8 * (lane >> 4);
        uint32_t base = (uint32_t)(arow * RSTRIDE + acol * 2);
#pragma unroll
        for (int g = 0; g < 4; g++) {
            ldsm_x4(qfh[mi][g], sb + O_QH + base + 32 * g);
            ldsm_x4(qfl[mi][g], sb + O_QL + base + 32 * g);
        }
    }

    const uint32_t boff = (uint32_t)((lane & 7) * RSTRIDE + (lane >> 3) * 16);

    float oacc[2][8][4];
#pragma unroll
    for (int mi = 0; mi < 2; mi++)
#pragma unroll
        for (int j = 0; j < 8; j++)
#pragma unroll
            for (int c = 0; c < 4; c++) oacc[mi][j][c] = 0.f;
    float lsum[2][2] = {{0.f, 0.f}, {0.f, 0.f}};

    for (int it = it0; it < it1; it++) {
        const uint32_t kvb = sb + O_KV + (uint32_t)(it & 1) * KVBUF;
        if (it + 1 < it1) {
            kv_load(sb + O_KV + (uint32_t)((it + 1) & 1) * KVBUF,
                    tid, b, (it + 1) * 64, kh, kl, vth, vtl);
            CP_COMMIT();
        }

#pragma unroll 1
        for (int half = 0; half < 2; half++) {
            // ---- S = (Qh+Ql)(Kh+Kl)^T for 32-key half: m32 x n32 ----
            float sacc[2][4][4];
#pragma unroll
            for (int mi = 0; mi < 2; mi++)
#pragma unroll
                for (int jj = 0; jj < 4; jj++)
#pragma unroll
                    for (int c = 0; c < 4; c++) sacc[mi][jj][c] = 0.f;

#pragma unroll
            for (int jj = 0; jj < 4; jj++) {
                int j = 4 * half + jj;
                uint32_t bh[8], bl[8];
                uint32_t kb = kvb + j * (8 * RSTRIDE) + boff;
                ldsm_x4(bh, kb);
                ldsm_x4(bh + 4, kb + 64);
                uint32_t lb = kvb + TILE_B + j * (8 * RSTRIDE) + boff;
                ldsm_x4(bl, lb);
                ldsm_x4(bl + 4, lb + 64);
#pragma unroll
                for (int mi = 0; mi < 2; mi++)
#pragma unroll
                    for (int s = 0; s < 4; s++) {
                        mma16816(sacc[mi][jj], qfh[mi][s], bh[2 * s], bh[2 * s + 1]);
                        mma16816(sacc[mi][jj], qfh[mi][s], bl[2 * s], bl[2 * s + 1]);
                        mma16816(sacc[mi][jj], qfl[mi][s], bh[2 * s], bh[2 * s + 1]);
                    }
            }

            // ---- exp (no max-sub), row sums, P fragments for k32 ----
            uint32_t pfh[2][2][4], pfl[2][2][4];
#pragma unroll
            for (int mi = 0; mi < 2; mi++)
#pragma unroll
                for (int sg = 0; sg < 2; sg++) {
                    float p[8];
                    p[0] = __expf(sacc[mi][2 * sg][0]);
                    p[1] = __expf(sacc[mi][2 * sg][1]);
                    p[2] = __expf(sacc[mi][2 * sg][2]);
                    p[3] = __expf(sacc[mi][2 * sg][3]);
                    p[4] = __expf(sacc[mi][2 * sg + 1][0]);
                    p[5] = __expf(sacc[mi][2 * sg + 1][1]);
                    p[6] = __expf(sacc[mi][2 * sg + 1][2]);
                    p[7] = __expf(sacc[mi][2 * sg + 1][3]);
                    lsum[mi][0] += (p[0] + p[1]) + (p[4] + p[5]);
                    lsum[mi][1] += (p[2] + p[3]) + (p[6] + p[7]);
#pragma unroll
                    for (int q = 0; q < 4; q++) {
                        float e0 = p[2 * q], e1 = p[2 * q + 1];
                        __nv_bfloat16 h0 = __float2bfloat16(e0);
                        __nv_bfloat16 h1 = __float2bfloat16(e1);
                        __nv_bfloat162 hp = __halves2bfloat162(h0, h1);
                        __nv_bfloat162 lp = __halves2bfloat162(
                            __float2bfloat16(e0 - __bfloat162float(h0)),
                            __float2bfloat16(e1 - __bfloat162float(h1)));
                        pfh[mi][sg][q] = *(uint32_t*)&hp;
                        pfl[mi][sg][q] = *(uint32_t*)&lp;
                    }
                }

            // ---- O += (Ph+Pl)(Vh+Vl) for this 32-key half ----
#pragma unroll
            for (int j = 0; j < 8; j++) {
                uint32_t vh[4], vl[4];
                uint32_t vb = kvb + 2 * TILE_B + j * (8 * RSTRIDE) + half * 64 + boff;
                ldsm_x4(vh, vb);
                ldsm_x4(vl, vb + TILE_B);
#pragma unroll
                for (int mi = 0; mi < 2; mi++)
#pragma unroll
                    for (int sg = 0; sg < 2; sg++) {
                        mma16816(oacc[mi][j], pfh[mi][sg], vh[2 * sg], vh[2 * sg + 1]);
                        mma16816(oacc[mi][j], pfh[mi][sg], vl[2 * sg], vl[2 * sg + 1]);
                        mma16816(oacc[mi][j], pfl[mi][sg], vh[2 * sg], vh[2 * sg + 1]);
                    }
            }
        }

        CP_WAIT_ALL();
        __syncthreads();
    }

    // ---- write partial O (unnormalized) + partial l ----
#pragma unroll
    for (int mi = 0; mi < 2; mi++) {
        float l0 = lsum[mi][0], l1 = lsum[mi][1];
        l0 += __shfl_xor_sync(0xffffffffu, l0, 1);
        l0 += __shfl_xor_sync(0xffffffffu, l0, 2);
        l1 += __shfl_xor_sync(0xffffffffu, l1, 1);
        l1 += __shfl_xor_sync(0xffffffffu, l1, 2);

        int row = 32 * w + 16 * mi + (lane >> 2);
        size_t rg = (size_t)b * LQ_ + q0 + row;
        float* ob = po + ((size_t)ks * NROW + rg) * DO_ + (lane & 3) * 2;
#pragma unroll
        for (int j = 0; j < 8; j++) {
            *(float2*)(ob + 8 * j) = make_float2(oacc[mi][j][0], oacc[mi][j][1]);
            *(float2*)(ob + 8 * j + 8 * DO_) = make_float2(oacc[mi][j][2], oacc[mi][j][3]);
        }
        if ((lane & 3) == 0) {
            pl[(size_t)ks * NROW + rg] = l0;
            pl[(size_t)ks * NROW + rg + 8] = l1;
        }
    }
}

// ---------------------------------------------------------------------------
// Reduce: out = (O0 + O1) / (l0 + l1)
// ---------------------------------------------------------------------------
__global__ __launch_bounds__(256) void reduce_kernel(
    const float* __restrict__ po, const float* __restrict__ pl,
    float* __restrict__ out)
{
    int idx = blockIdx.x * 256 + threadIdx.x;    // float4 index, 262144 total
    int row = idx >> 4;                          // 16 float4 per row
    float inv = 1.0f / (pl[row] + pl[NROW + row]);
    const float4* p0 = (const float4*)po;
    float4 a = p0[idx];
    float4 b = p0[idx + NROW * DO_ / 4];
    float4 r = make_float4((a.x + b.x) * inv, (a.y + b.y) * inv,
                           (a.z + b.z) * inv, (a.w + b.w) * inv);
    ((float4*)out)[idx] = r;
}

// ---------------------------------------------------------------------------
extern "C" void kernel_launch(void* const* d_in, const int* in_sizes, int n_in,
                              void* d_out, int out_size)
{
    const float* query = (const float*)d_in[0];
    const float* key   = (const float*)d_in[1];
    const float* Wq    = (const float*)d_in[2];
    const float* Wk    = (const float*)d_in[3];
    const float* Wv    = (const float*)d_in[4];
    float* out = (float*)d_out;

    __nv_bfloat16 *qh, *ql, *khp, *klp, *vth, *vtl;
    float *po, *pl;
    cudaGetSymbolAddress((void**)&qh, g_qh);
    cudaGetSymbolAddress((void**)&ql, g_ql);
    cudaGetSymbolAddress((void**)&khp, g_kh);
    cudaGetSymbolAddress((void**)&klp, g_kl);
    cudaGetSymbolAddress((void**)&vth, g_vth);
    cudaGetSymbolAddress((void**)&vtl, g_vtl);
    cudaGetSymbolAddress((void**)&po, g_po);
    cudaGetSymbolAddress((void**)&pl, g_pl);

    proj_all_kernel<<<512, 256>>>(query, key, Wq, Wk, Wv,
                                  qh, ql, khp, klp, vth, vtl);

    cudaFuncSetAttribute(attn_mma_kernel,
                         cudaFuncAttributeMaxDynamicSharedMemorySize, SM_BYTES);
    dim3 grid(LQ_ / 128, B_, 2);   // (16, 8, 2) = 256 CTAs, 2 per SM
    attn_mma_kernel<<<grid, 128, SM_BYTES>>>(qh, ql, khp, klp, vth, vtl, po, pl);

    reduce_kernel<<<(NROW * DO_ / 4) / 256, 256>>>(po, pl, out);
}

// round 10
// speedup vs baseline: 2.9360x; 1.1299x over previous
#include <cuda_runtime.h>
#include <cuda_bf16.h>
#include <math.h>
#include <stdint.h>

// Problem constants
#define B_   8
#define LQ_  2048
#define LK_  2048
#define DIN_ 128
#define DO_  64
#define NROW (B_ * LQ_)   // 16384

typedef unsigned long long u64;

// ---- tensor-core + async primitives (baseline PTX, OK for plain sm_103) ---
__device__ __forceinline__ void ldsm_x4(uint32_t* r, uint32_t addr) {
    asm volatile("ldmatrix.sync.aligned.m8n8.x4.shared.b16 {%0,%1,%2,%3}, [%4];"
        : "=r"(r[0]), "=r"(r[1]), "=r"(r[2]), "=r"(r[3]) : "r"(addr));
}
__device__ __forceinline__ void mma16816(float* d, const uint32_t* a,
                                         uint32_t b0, uint32_t b1) {
    asm volatile(
        "mma.sync.aligned.m16n8k16.row.col.f32.bf16.bf16.f32 "
        "{%0,%1,%2,%3}, {%4,%5,%6,%7}, {%8,%9}, {%0,%1,%2,%3};"
        : "+f"(d[0]), "+f"(d[1]), "+f"(d[2]), "+f"(d[3])
        : "r"(a[0]), "r"(a[1]), "r"(a[2]), "r"(a[3]), "r"(b0), "r"(b1));
}
__device__ __forceinline__ uint32_t smem_u32(const void* p) {
    uint32_t a;
    asm("{ .reg .u64 t; cvta.to.shared.u64 t, %1; cvt.u32.u64 %0, t; }"
        : "=r"(a) : "l"(p));
    return a;
}
__device__ __forceinline__ void cp_async16(uint32_t dst, const void* src) {
    asm volatile("cp.async.ca.shared.global [%0], [%1], 16;"
                 :: "r"(dst), "l"(src) : "memory");
}
#define CP_COMMIT()   asm volatile("cp.async.commit_group;" ::: "memory")
#define CP_WAIT_ALL() asm volatile("cp.async.wait_group 0;" ::: "memory")

// pack two floats -> bf16x2 (lo = first memory element)
__device__ __forceinline__ uint32_t pkbf(float lo, float hi) {
    uint32_t r;
    asm("cvt.rn.bf16x2.f32 %0, %1, %2;" : "=r"(r) : "f"(hi), "f"(lo));
    return r;
}
// hi/lo split of a float pair into two bf16x2 words
__device__ __forceinline__ void split_pair(float x, float y,
                                           uint32_t& hp, uint32_t& lp) {
    hp = pkbf(x, y);
    float hx = __uint_as_float(hp << 16);
    float hy = __uint_as_float(hp & 0xFFFF0000u);
    lp = pkbf(x - hx, y - hy);
}

// ---- Scratch ---------------------------------------------------------------
__device__ __nv_bfloat16 g_qh[NROW * DO_];
__device__ __nv_bfloat16 g_ql[NROW * DO_];
__device__ __nv_bfloat16 g_kh[NROW * DO_];
__device__ __nv_bfloat16 g_kl[NROW * DO_];
__device__ __nv_bfloat16 g_vth[B_ * DO_ * LK_];   // [b][dim][key]
__device__ __nv_bfloat16 g_vtl[B_ * DO_ * LK_];
__device__ float g_po[2 * NROW * DO_];
__device__ float g_pl[2 * NROW];

// ---------------------------------------------------------------------------
// Tensor-core projections. Grid 256 x 128 threads.
// CTA < 128: Q path (rows 128*cta of query -> Q).  CTA >= 128: K+V path.
// Stage A (fp32->bf16 hi/lo) and W^T (hi/lo) in smem, then split-bf16 mma.
// ---------------------------------------------------------------------------
#define RSA 272                      // A row stride bytes (128 cols + 8 pad)
#define RSW 272                      // Wt row stride bytes (128 cols + 8 pad)
#define P_AH   0
#define P_AL   (128 * RSA)           // 34816
#define P_W1H  (2 * 128 * RSA)       // 69632
#define P_W1L  (P_W1H + 64 * RSW)    // 87040
#define P_W2H  (P_W1L + 64 * RSW)    // 104448
#define P_W2L  (P_W2H + 64 * RSW)    // 121856
#define P_SMEM (P_W2L + 64 * RSW)    // 139264

// compute sacc = A(128x128) @ Wt^T for this warp (m32 x n64), split-bf16
__device__ __forceinline__ void proj_mma_compute(
    uint32_t sb, uint32_t o_wh, uint32_t o_wl, int w, int lane,
    float sacc[2][8][4])
{
#pragma unroll
    for (int mi = 0; mi < 2; mi++)
#pragma unroll
        for (int j = 0; j < 8; j++)
#pragma unroll
            for (int c = 0; c < 4; c++) sacc[mi][j][c] = 0.f;

    const uint32_t a_base0 = sb + P_AH +
        (uint32_t)((32 * w + (lane & 7) + 8 * ((lane >> 3) & 1)) * RSA +
                   (lane >> 4) * 16);
    const uint32_t b_off = (uint32_t)((lane & 15) * RSW + (lane >> 4) * 16);

#pragma unroll
    for (int g = 0; g < 8; g++) {
        uint32_t ah[2][4], al[2][4];
#pragma unroll
        for (int mi = 0; mi < 2; mi++) {
            uint32_t aa = a_base0 + mi * (16 * RSA) + 32 * g;
            ldsm_x4(ah[mi], aa);
            ldsm_x4(al[mi], aa + (P_AL - P_AH));
        }
#pragma unroll
        for (int j2 = 0; j2 < 4; j2++) {
            uint32_t bh[4], bl[4];
            uint32_t ba = sb + o_wh + j2 * (16 * RSW) + b_off + 32 * g;
            ldsm_x4(bh, ba);
            ldsm_x4(bl, ba + (o_wl - o_wh));
#pragma unroll
            for (int mi = 0; mi < 2; mi++)
#pragma unroll
                for (int js = 0; js < 2; js++) {
                    float* acc = sacc[mi][2 * j2 + js];
                    mma16816(acc, ah[mi], bh[js], bh[js + 2]);
                    mma16816(acc, ah[mi], bl[js], bl[js + 2]);
                    mma16816(acc, al[mi], bh[js], bh[js + 2]);
                }
        }
    }
}

__global__ __launch_bounds__(128) void proj_mma_kernel(
    const float* __restrict__ query, const float* __restrict__ key,
    const float* __restrict__ Wq, const float* __restrict__ Wk,
    const float* __restrict__ Wv,
    __nv_bfloat16* __restrict__ oqh, __nv_bfloat16* __restrict__ oql,
    __nv_bfloat16* __restrict__ okh, __nv_bfloat16* __restrict__ okl,
    __nv_bfloat16* __restrict__ ovh, __nv_bfloat16* __restrict__ ovl)
{
    extern __shared__ __align__(16) char sm[];
    const uint32_t sb = smem_u32(sm);

    const int tid = threadIdx.x;
    const int w = tid >> 5;
    const int lane = tid & 31;
    const bool qpath = blockIdx.x < 128;
    const size_t row0 = (size_t)(qpath ? blockIdx.x : blockIdx.x - 128) * 128;
    const float* A = qpath ? query : key;

    // ---- stage A: 8192 float2, coalesced; convert to bf16 hi/lo ----
#pragma unroll 4
    for (int n = 0; n < 64; n++) {
        int idx = tid + n * 128;           // float2 index
        int r = idx >> 6, c = idx & 63;
        float2 a = ((const float2*)A)[(row0 + r) * (DIN_ / 2) + c];
        uint32_t hp, lp;
        split_pair(a.x, a.y, hp, lp);
        *(uint32_t*)(sm + P_AH + r * RSA + c * 4) = hp;
        *(uint32_t*)(sm + P_AL + r * RSA + c * 4) = lp;
    }
    // ---- stage W^T hi/lo (scattered 2B smem stores; small) ----
    {
        const float* W1 = qpath ? Wq : Wk;
#pragma unroll 4
        for (int n = 0; n < 64; n++) {
            int idx = tid + n * 128;       // element index, 8192
            int k = idx >> 6, c = idx & 63;
            float v = W1[k * DO_ + c];
            __nv_bfloat16 h = __float2bfloat16(v);
            __nv_bfloat16 l = __float2bfloat16(v - __bfloat162float(h));
            *(__nv_bfloat16*)(sm + P_W1H + c * RSW + k * 2) = h;
            *(__nv_bfloat16*)(sm + P_W1L + c * RSW + k * 2) = l;
        }
        if (!qpath) {
#pragma unroll 4
            for (int n = 0; n < 64; n++) {
                int idx = tid + n * 128;
                int k = idx >> 6, c = idx & 63;
                float v = Wv[k * DO_ + c];
                __nv_bfloat16 h = __float2bfloat16(v);
                __nv_bfloat16 l = __float2bfloat16(v - __bfloat162float(h));
                *(__nv_bfloat16*)(sm + P_W2H + c * RSW + k * 2) = h;
                *(__nv_bfloat16*)(sm + P_W2L + c * RSW + k * 2) = l;
            }
        }
    }
    __syncthreads();

    float sacc[2][8][4];

    // ---- output 1: Q or K (row-major hi/lo) ----
    proj_mma_compute(sb, P_W1H, P_W1L, w, lane, sacc);
    {
        __nv_bfloat16* oh = qpath ? oqh : okh;
        __nv_bfloat16* ol = qpath ? oql : okl;
#pragma unroll
        for (int mi = 0; mi < 2; mi++) {
            int r0 = 32 * w + 16 * mi + (lane >> 2);
#pragma unroll
            for (int j = 0; j < 8; j++) {
                int c0 = 8 * j + (lane & 3) * 2;
                uint32_t hp, lp;
                split_pair(sacc[mi][j][0], sacc[mi][j][1], hp, lp);
                *(uint32_t*)&oh[(row0 + r0) * DO_ + c0] = hp;
                *(uint32_t*)&ol[(row0 + r0) * DO_ + c0] = lp;
                split_pair(sacc[mi][j][2], sacc[mi][j][3], hp, lp);
                *(uint32_t*)&oh[(row0 + r0 + 8) * DO_ + c0] = hp;
                *(uint32_t*)&ol[(row0 + r0 + 8) * DO_ + c0] = lp;
            }
        }
    }

    // ---- output 2 (KV path only): V, stored transposed [b][dim][key] ----
    if (!qpath) {
        proj_mma_compute(sb, P_W2H, P_W2L, w, lane, sacc);
        const size_t bb = row0 >> 11;
        const int k0 = (int)(row0 & 2047);
        unsigned short* vh = (unsigned short*)ovh;
        unsigned short* vl = (unsigned short*)ovl;
#pragma unroll
        for (int mi = 0; mi < 2; mi++) {
            int r0 = 32 * w + 16 * mi + (lane >> 2);
#pragma unroll
            for (int j = 0; j < 8; j++) {
                int c0 = 8 * j + (lane & 3) * 2;
                uint32_t hp, lp;
                split_pair(sacc[mi][j][0], sacc[mi][j][1], hp, lp);
                size_t base = (bb * DO_ + c0) * (size_t)LK_ + k0 + r0;
                vh[base] = (unsigned short)(hp & 0xFFFF);
                vh[base + LK_] = (unsigned short)(hp >> 16);
                vl[base] = (unsigned short)(lp & 0xFFFF);
                vl[base + LK_] = (unsigned short)(lp >> 16);
                split_pair(sacc[mi][j][2], sacc[mi][j][3], hp, lp);
                vh[base + 8] = (unsigned short)(hp & 0xFFFF);
                vh[base + LK_ + 8] = (unsigned short)(hp >> 16);
                vl[base + 8] = (unsigned short)(lp & 0xFFFF);
                vl[base + LK_ + 8] = (unsigned short)(lp >> 16);
            }
        }
    }
}

// ---------------------------------------------------------------------------
// mma.sync flash attention (unchanged from R9). BQ=128, 4 warps, key-split x2.
// ---------------------------------------------------------------------------
#define RSTRIDE 144
#define TILE_B  (64 * RSTRIDE)
#define QTILE_B (128 * RSTRIDE)
#define O_QH  0
#define O_QL  QTILE_B
#define O_KV  (2 * QTILE_B)
#define KVBUF (4 * TILE_B)
#define SM_BYTES (O_KV + 2 * KVBUF)   // 110592

__device__ __forceinline__ void kv_load(
    uint32_t dstbase, int tid, int b, int kt,
    const __nv_bfloat16* __restrict__ kh, const __nv_bfloat16* __restrict__ kl,
    const __nv_bfloat16* __restrict__ vth, const __nv_bfloat16* __restrict__ vtl)
{
#pragma unroll
    for (int n = 0; n < 16; n++) {
        int i = tid + n * 128;
        int t = i >> 9, r = (i >> 3) & 63, c = i & 7;
        const __nv_bfloat16* src;
        if (t == 0)      src = kh  + ((size_t)b * LK_ + kt + r) * DO_ + c * 8;
        else if (t == 1) src = kl  + ((size_t)b * LK_ + kt + r) * DO_ + c * 8;
        else if (t == 2) src = vth + ((size_t)b * DO_ + r) * LK_ + kt + c * 8;
        else             src = vtl + ((size_t)b * DO_ + r) * LK_ + kt + c * 8;
        cp_async16(dstbase + t * TILE_B + r * RSTRIDE + c * 16, src);
    }
}

__global__ __launch_bounds__(128, 2) void attn_mma_kernel(
    const __nv_bfloat16* __restrict__ qh, const __nv_bfloat16* __restrict__ ql,
    const __nv_bfloat16* __restrict__ kh, const __nv_bfloat16* __restrict__ kl,
    const __nv_bfloat16* __restrict__ vth, const __nv_bfloat16* __restrict__ vtl,
    float* __restrict__ po, float* __restrict__ pl)
{
    extern __shared__ __align__(16) char sm[];
    const uint32_t sb = smem_u32(sm);

    const int tid = threadIdx.x;
    const int w = tid >> 5;
    const int lane = tid & 31;
    const int b = blockIdx.y;
    const int ks = blockIdx.z;
    const int it0 = ks * (LK_ / 128);
    const int it1 = it0 + (LK_ / 128);
    const size_t q0 = (size_t)blockIdx.x * 128;

#pragma unroll
    for (int n = 0; n < 16; n++) {
        int i = tid + n * 128;
        int t = i >> 10, r = (i >> 3) & 127, c = i & 7;
        const __nv_bfloat16* src =
            (t ? ql : qh) + ((size_t)b * LQ_ + q0 + r) * DO_ + c * 8;
        cp_async16(sb + (t ? O_QL : O_QH) + r * RSTRIDE + c * 16, src);
    }
    kv_load(sb + O_KV, tid, b, it0 * 64, kh, kl, vth, vtl);
    CP_COMMIT();
    CP_WAIT_ALL();
    __syncthreads();

    uint32_t qfh[2][4][4], qfl[2][4][4];
#pragma unroll
    for (int mi = 0; mi < 2; mi++) {
        int arow = 32 * w + 16 * mi + (lane & 7) + 8 * ((lane >> 3) & 1);
        int acol = 8 * (lane >> 4);
        uint32_t base = (uint32_t)(arow * RSTRIDE + acol * 2);
#pragma unroll
        for (int g = 0; g < 4; g++) {
            ldsm_x4(qfh[mi][g], sb + O_QH + base + 32 * g);
            ldsm_x4(qfl[mi][g], sb + O_QL + base + 32 * g);
        }
    }

    const uint32_t boff = (uint32_t)((lane & 7) * RSTRIDE + (lane >> 3) * 16);

    float oacc[2][8][4];
#pragma unroll
    for (int mi = 0; mi < 2; mi++)
#pragma unroll
        for (int j = 0; j < 8; j++)
#pragma unroll
            for (int c = 0; c < 4; c++) oacc[mi][j][c] = 0.f;
    float lsum[2][2] = {{0.f, 0.f}, {0.f, 0.f}};

    for (int it = it0; it < it1; it++) {
        const uint32_t kvb = sb + O_KV + (uint32_t)(it & 1) * KVBUF;
        if (it + 1 < it1) {
            kv_load(sb + O_KV + (uint32_t)((it + 1) & 1) * KVBUF,
                    tid, b, (it + 1) * 64, kh, kl, vth, vtl);
            CP_COMMIT();
        }

#pragma unroll 1
        for (int half = 0; half < 2; half++) {
            float sacc[2][4][4];
#pragma unroll
            for (int mi = 0; mi < 2; mi++)
#pragma unroll
                for (int jj = 0; jj < 4; jj++)
#pragma unroll
                    for (int c = 0; c < 4; c++) sacc[mi][jj][c] = 0.f;

#pragma unroll
            for (int jj = 0; jj < 4; jj++) {
                int j = 4 * half + jj;
                uint32_t bh[8], bl[8];
                uint32_t kb = kvb + j * (8 * RSTRIDE) + boff;
                ldsm_x4(bh, kb);
                ldsm_x4(bh + 4, kb + 64);
                uint32_t lb = kvb + TILE_B + j * (8 * RSTRIDE) + boff;
                ldsm_x4(bl, lb);
                ldsm_x4(bl + 4, lb + 64);
#pragma unroll
                for (int mi = 0; mi < 2; mi++)
#pragma unroll
                    for (int s = 0; s < 4; s++) {
                        mma16816(sacc[mi][jj], qfh[mi][s], bh[2 * s], bh[2 * s + 1]);
                        mma16816(sacc[mi][jj], qfh[mi][s], bl[2 * s], bl[2 * s + 1]);
                        mma16816(sacc[mi][jj], qfl[mi][s], bh[2 * s], bh[2 * s + 1]);
                    }
            }

            uint32_t pfh[2][2][4], pfl[2][2][4];
#pragma unroll
            for (int mi = 0; mi < 2; mi++)
#pragma unroll
                for (int sg = 0; sg < 2; sg++) {
                    float p[8];
                    p[0] = __expf(sacc[mi][2 * sg][0]);
                    p[1] = __expf(sacc[mi][2 * sg][1]);
                    p[2] = __expf(sacc[mi][2 * sg][2]);
                    p[3] = __expf(sacc[mi][2 * sg][3]);
                    p[4] = __expf(sacc[mi][2 * sg + 1][0]);
                    p[5] = __expf(sacc[mi][2 * sg + 1][1]);
                    p[6] = __expf(sacc[mi][2 * sg + 1][2]);
                    p[7] = __expf(sacc[mi][2 * sg + 1][3]);
                    lsum[mi][0] += (p[0] + p[1]) + (p[4] + p[5]);
                    lsum[mi][1] += (p[2] + p[3]) + (p[6] + p[7]);
#pragma unroll
                    for (int q = 0; q < 4; q++) {
                        uint32_t hp, lp;
                        split_pair(p[2 * q], p[2 * q + 1], hp, lp);
                        pfh[mi][sg][q] = hp;
                        pfl[mi][sg][q] = lp;
                    }
                }

#pragma unroll
            for (int j = 0; j < 8; j++) {
                uint32_t vh[4], vl[4];
                uint32_t vb = kvb + 2 * TILE_B + j * (8 * RSTRIDE) + half * 64 + boff;
                ldsm_x4(vh, vb);
                ldsm_x4(vl, vb + TILE_B);
#pragma unroll
                for (int mi = 0; mi < 2; mi++)
#pragma unroll
                    for (int sg = 0; sg < 2; sg++) {
                        mma16816(oacc[mi][j], pfh[mi][sg], vh[2 * sg], vh[2 * sg + 1]);
                        mma16816(oacc[mi][j], pfh[mi][sg], vl[2 * sg], vl[2 * sg + 1]);
                        mma16816(oacc[mi][j], pfl[mi][sg], vh[2 * sg], vh[2 * sg + 1]);
                    }
            }
        }

        CP_WAIT_ALL();
        __syncthreads();
    }

#pragma unroll
    for (int mi = 0; mi < 2; mi++) {
        float l0 = lsum[mi][0], l1 = lsum[mi][1];
        l0 += __shfl_xor_sync(0xffffffffu, l0, 1);
        l0 += __shfl_xor_sync(0xffffffffu, l0, 2);
        l1 += __shfl_xor_sync(0xffffffffu, l1, 1);
        l1 += __shfl_xor_sync(0xffffffffu, l1, 2);

        int row = 32 * w + 16 * mi + (lane >> 2);
        size_t rg = (size_t)b * LQ_ + q0 + row;
        float* ob = po + ((size_t)ks * NROW + rg) * DO_ + (lane & 3) * 2;
#pragma unroll
        for (int j = 0; j < 8; j++) {
            *(float2*)(ob + 8 * j) = make_float2(oacc[mi][j][0], oacc[mi][j][1]);
            *(float2*)(ob + 8 * j + 8 * DO_) = make_float2(oacc[mi][j][2], oacc[mi][j][3]);
        }
        if ((lane & 3) == 0) {
            pl[(size_t)ks * NROW + rg] = l0;
            pl[(size_t)ks * NROW + rg + 8] = l1;
        }
    }
}

// ---------------------------------------------------------------------------
__global__ __launch_bounds__(256) void reduce_kernel(
    const float* __restrict__ po, const float* __restrict__ pl,
    float* __restrict__ out)
{
    int idx = blockIdx.x * 256 + threadIdx.x;
    int row = idx >> 4;
    float inv = 1.0f / (pl[row] + pl[NROW + row]);
    const float4* p0 = (const float4*)po;
    float4 a = p0[idx];
    float4 b = p0[idx + NROW * DO_ / 4];
    float4 r = make_float4((a.x + b.x) * inv, (a.y + b.y) * inv,
                           (a.z + b.z) * inv, (a.w + b.w) * inv);
    ((float4*)out)[idx] = r;
}

// ---------------------------------------------------------------------------
extern "C" void kernel_launch(void* const* d_in, const int* in_sizes, int n_in,
                              void* d_out, int out_size)
{
    const float* query = (const float*)d_in[0];
    const float* key   = (const float*)d_in[1];
    const float* Wq    = (const float*)d_in[2];
    const float* Wk    = (const float*)d_in[3];
    const float* Wv    = (const float*)d_in[4];
    float* out = (float*)d_out;

    __nv_bfloat16 *qh, *ql, *khp, *klp, *vth, *vtl;
    float *po, *pl;
    cudaGetSymbolAddress((void**)&qh, g_qh);
    cudaGetSymbolAddress((void**)&ql, g_ql);
    cudaGetSymbolAddress((void**)&khp, g_kh);
    cudaGetSymbolAddress((void**)&klp, g_kl);
    cudaGetSymbolAddress((void**)&vth, g_vth);
    cudaGetSymbolAddress((void**)&vtl, g_vtl);
    cudaGetSymbolAddress((void**)&po, g_po);
    cudaGetSymbolAddress((void**)&pl, g_pl);

    cudaFuncSetAttribute(proj_mma_kernel,
                         cudaFuncAttributeMaxDynamicSharedMemorySize, P_SMEM);
    proj_mma_kernel<<<256, 128, P_SMEM>>>(query, key, Wq, Wk, Wv,
                                          qh, ql, khp, klp, vth, vtl);

    cudaFuncSetAttribute(attn_mma_kernel,
                         cudaFuncAttributeMaxDynamicSharedMemorySize, SM_BYTES);
    dim3 grid(LQ_ / 128, B_, 2);
    attn_mma_kernel<<<grid, 128, SM_BYTES>>>(qh, ql, khp, klp, vth, vtl, po, pl);

    reduce_kernel<<<(NROW * DO_ / 4) / 256, 256>>>(po, pl, out);
}

// round 11
// speedup vs baseline: 3.2927x; 1.1215x over previous
#include <cuda_runtime.h>
#include <cuda_bf16.h>
#include <math.h>
#include <stdint.h>

// Problem constants
#define B_   8
#define LQ_  2048
#define LK_  2048
#define DIN_ 128
#define DO_  64
#define NROW (B_ * LQ_)   // 16384

typedef unsigned long long u64;

// ---- tensor-core + async primitives (baseline PTX, OK for plain sm_103) ---
__device__ __forceinline__ void ldsm_x4(uint32_t* r, uint32_t addr) {
    asm volatile("ldmatrix.sync.aligned.m8n8.x4.shared.b16 {%0,%1,%2,%3}, [%4];"
        : "=r"(r[0]), "=r"(r[1]), "=r"(r[2]), "=r"(r[3]) : "r"(addr));
}
__device__ __forceinline__ void mma16816(float* d, const uint32_t* a,
                                         uint32_t b0, uint32_t b1) {
    asm volatile(
        "mma.sync.aligned.m16n8k16.row.col.f32.bf16.bf16.f32 "
        "{%0,%1,%2,%3}, {%4,%5,%6,%7}, {%8,%9}, {%0,%1,%2,%3};"
        : "+f"(d[0]), "+f"(d[1]), "+f"(d[2]), "+f"(d[3])
        : "r"(a[0]), "r"(a[1]), "r"(a[2]), "r"(a[3]), "r"(b0), "r"(b1));
}
__device__ __forceinline__ uint32_t smem_u32(const void* p) {
    uint32_t a;
    asm("{ .reg .u64 t; cvta.to.shared.u64 t, %1; cvt.u32.u64 %0, t; }"
        : "=r"(a) : "l"(p));
    return a;
}
__device__ __forceinline__ void cp_async16(uint32_t dst, const void* src) {
    asm volatile("cp.async.ca.shared.global [%0], [%1], 16;"
                 :: "r"(dst), "l"(src) : "memory");
}
#define CP_COMMIT()   asm volatile("cp.async.commit_group;" ::: "memory")
#define CP_WAIT_ALL() asm volatile("cp.async.wait_group 0;" ::: "memory")

// pack two floats -> bf16x2 (lo = first memory element)
__device__ __forceinline__ uint32_t pkbf(float lo, float hi) {
    uint32_t r;
    asm("cvt.rn.bf16x2.f32 %0, %1, %2;" : "=r"(r) : "f"(hi), "f"(lo));
    return r;
}
__device__ __forceinline__ void split_pair(float x, float y,
                                           uint32_t& hp, uint32_t& lp) {
    hp = pkbf(x, y);
    float hx = __uint_as_float(hp << 16);
    float hy = __uint_as_float(hp & 0xFFFF0000u);
    lp = pkbf(x - hx, y - hy);
}

// ---- Scratch ---------------------------------------------------------------
__device__ __nv_bfloat16 g_qh[NROW * DO_];
__device__ __nv_bfloat16 g_ql[NROW * DO_];
__device__ __nv_bfloat16 g_kh[NROW * DO_];
__device__ __nv_bfloat16 g_kl[NROW * DO_];
__device__ __nv_bfloat16 g_vth[B_ * DO_ * LK_];   // [b][dim][key]
__device__ __nv_bfloat16 g_vtl[B_ * DO_ * LK_];
__device__ float g_po[2 * NROW * DO_];
__device__ float g_pl[2 * NROW];

// ---------------------------------------------------------------------------
// Tensor-core projections. Grid 384 x 256 threads, 2 CTAs/SM.
// Path 0 (blk 0-127): Q.  Path 1 (128-255): K.  Path 2 (256-383): V (transposed).
// CTA = 128 input rows, 8 warps (warp = m16 x n64), one weight matrix.
// ---------------------------------------------------------------------------
#define RSA 272                      // row stride bytes (128 bf16 + 8 pad)
#define PR_AH 0
#define PR_AL (128 * RSA)            // 34816
#define PR_WH (2 * 128 * RSA)        // 69632
#define PR_WL (PR_WH + 64 * RSA)     // 87040
#define PR_SMEM (PR_WL + 64 * RSA)   // 104448

__global__ __launch_bounds__(256, 2) void proj_mma_kernel(
    const float* __restrict__ query, const float* __restrict__ key,
    const float* __restrict__ Wq, const float* __restrict__ Wk,
    const float* __restrict__ Wv,
    __nv_bfloat16* __restrict__ oqh, __nv_bfloat16* __restrict__ oql,
    __nv_bfloat16* __restrict__ okh, __nv_bfloat16* __restrict__ okl,
    __nv_bfloat16* __restrict__ ovh, __nv_bfloat16* __restrict__ ovl)
{
    extern __shared__ __align__(16) char sm[];
    const uint32_t sb = smem_u32(sm);

    const int tid = threadIdx.x;
    const int w = tid >> 5;
    const int lane = tid & 31;
    const int path = blockIdx.x >> 7;          // 0=Q, 1=K, 2=V
    const size_t row0 = (size_t)(blockIdx.x & 127) * 128;
    const float* A = (path == 0) ? query : key;
    const float* W = (path == 0) ? Wq : (path == 1) ? Wk : Wv;

    // ---- stage A (fp32 -> bf16 hi/lo), 8192 float2, coalesced ----
#pragma unroll 8
    for (int n = 0; n < 32; n++) {
        int idx = tid + n * 256;           // float2 index
        int r = idx >> 6, c = idx & 63;
        float2 a = ((const float2*)A)[(row0 + r) * (DIN_ / 2) + c];
        uint32_t hp, lp;
        split_pair(a.x, a.y, hp, lp);
        *(uint32_t*)(sm + PR_AH + r * RSA + c * 4) = hp;
        *(uint32_t*)(sm + PR_AL + r * RSA + c * 4) = lp;
    }
    // ---- stage W^T hi/lo ----
#pragma unroll 8
    for (int n = 0; n < 32; n++) {
        int idx = tid + n * 256;           // element index, 8192
        int k = idx >> 6, c = idx & 63;
        float v = W[k * DO_ + c];
        __nv_bfloat16 h = __float2bfloat16(v);
        __nv_bfloat16 l = __float2bfloat16(v - __bfloat162float(h));
        *(__nv_bfloat16*)(sm + PR_WH + c * RSA + k * 2) = h;
        *(__nv_bfloat16*)(sm + PR_WL + c * RSA + k * 2) = l;
    }
    __syncthreads();

    // ---- warp m16 x n64 split-bf16 GEMM over K=128 ----
    float sacc[8][4];
#pragma unroll
    for (int j = 0; j < 8; j++)
#pragma unroll
        for (int c = 0; c < 4; c++) sacc[j][c] = 0.f;

    const uint32_t a_base = sb + PR_AH +
        (uint32_t)((16 * w + (lane & 15)) * RSA + (lane >> 4) * 16);
    const uint32_t b_off = (uint32_t)((lane & 15) * RSA + (lane >> 4) * 16);

#pragma unroll
    for (int g = 0; g < 8; g++) {
        uint32_t ah[4], al[4];
        ldsm_x4(ah, a_base + 32 * g);
        ldsm_x4(al, a_base + (PR_AL - PR_AH) + 32 * g);
#pragma unroll
        for (int j2 = 0; j2 < 4; j2++) {
            uint32_t bh[4], bl[4];
            uint32_t ba = sb + PR_WH + j2 * (16 * RSA) + b_off + 32 * g;
            ldsm_x4(bh, ba);
            ldsm_x4(bl, ba + (PR_WL - PR_WH));
#pragma unroll
            for (int js = 0; js < 2; js++) {
                float* acc = sacc[2 * j2 + js];
                mma16816(acc, ah, bh[js], bh[js + 2]);
                mma16816(acc, ah, bl[js], bl[js + 2]);
                mma16816(acc, al, bh[js], bh[js + 2]);
            }
        }
    }

    if (path < 2) {
        // ---- Q/K epilogue: row-major hi/lo, coalesced u32 stores ----
        __nv_bfloat16* oh = (path == 0) ? oqh : okh;
        __nv_bfloat16* ol = (path == 0) ? oql : okl;
        int r0 = 16 * w + (lane >> 2);
#pragma unroll
        for (int j = 0; j < 8; j++) {
            int c0 = 8 * j + (lane & 3) * 2;
            uint32_t hp, lp;
            split_pair(sacc[j][0], sacc[j][1], hp, lp);
            *(uint32_t*)&oh[(row0 + r0) * DO_ + c0] = hp;
            *(uint32_t*)&ol[(row0 + r0) * DO_ + c0] = lp;
            split_pair(sacc[j][2], sacc[j][3], hp, lp);
            *(uint32_t*)&oh[(row0 + r0 + 8) * DO_ + c0] = hp;
            *(uint32_t*)&ol[(row0 + r0 + 8) * DO_ + c0] = lp;
        }
    } else {
        // ---- V epilogue: transpose via smem (reuse A region), then
        //      coalesced uint4 stores to [b][dim][key] ----
        __syncthreads();   // all warps done reading A smem
        int key0 = 16 * w + (lane >> 2);
#pragma unroll
        for (int j = 0; j < 8; j++) {
            int c0 = 8 * j + (lane & 3) * 2;
            uint32_t hp, lp;
            split_pair(sacc[j][0], sacc[j][1], hp, lp);
            // hi buffer at PR_AH: [dim c][key] stride RSA; lo at PR_AL
            *(__nv_bfloat16*)(sm + PR_AH + c0 * RSA + key0 * 2) =
                __ushort_as_bfloat16((unsigned short)(hp & 0xFFFF));
            *(__nv_bfloat16*)(sm + PR_AH + (c0 + 1) * RSA + key0 * 2) =
                __ushort_as_bfloat16((unsigned short)(hp >> 16));
            *(__nv_bfloat16*)(sm + PR_AL + c0 * RSA + key0 * 2) =
                __ushort_as_bfloat16((unsigned short)(lp & 0xFFFF));
            *(__nv_bfloat16*)(sm + PR_AL + (c0 + 1) * RSA + key0 * 2) =
                __ushort_as_bfloat16((unsigned short)(lp >> 16));
            split_pair(sacc[j][2], sacc[j][3], hp, lp);
            *(__nv_bfloat16*)(sm + PR_AH + c0 * RSA + (key0 + 8) * 2) =
                __ushort_as_bfloat16((unsigned short)(hp & 0xFFFF));
            *(__nv_bfloat16*)(sm + PR_AH + (c0 + 1) * RSA + (key0 + 8) * 2) =
                __ushort_as_bfloat16((unsigned short)(hp >> 16));
            *(__nv_bfloat16*)(sm + PR_AL + c0 * RSA + (key0 + 8) * 2) =
                __ushort_as_bfloat16((unsigned short)(lp & 0xFFFF));
            *(__nv_bfloat16*)(sm + PR_AL + (c0 + 1) * RSA + (key0 + 8) * 2) =
                __ushort_as_bfloat16((unsigned short)(lp >> 16));
        }
        __syncthreads();
        const size_t bb = row0 >> 11;
        const int k0 = (int)(row0 & 2047);
        // 64 dims x 16 uint4 (128 keys) per buffer; 256 threads -> 4 iters each
#pragma unroll
        for (int n = 0; n < 4; n++) {
            int idx = tid + n * 256;
            int d = idx >> 4, c = idx & 15;
            uint4 vh = *(const uint4*)(sm + PR_AH + d * RSA + c * 16);
            uint4 vl = *(const uint4*)(sm + PR_AL + d * RSA + c * 16);
            size_t dst = (bb * DO_ + d) * (size_t)LK_ + k0 + c * 8;
            *(uint4*)&ovh[dst] = vh;
            *(uint4*)&ovl[dst] = vl;
        }
    }
}

// ---------------------------------------------------------------------------
// mma.sync flash attention (unchanged from R10). BQ=128, 4 warps, key-split x2.
// ---------------------------------------------------------------------------
#define RSTRIDE 144
#define TILE_B  (64 * RSTRIDE)
#define QTILE_B (128 * RSTRIDE)
#define O_QH  0
#define O_QL  QTILE_B
#define O_KV  (2 * QTILE_B)
#define KVBUF (4 * TILE_B)
#define SM_BYTES (O_KV + 2 * KVBUF)   // 110592

__device__ __forceinline__ void kv_load(
    uint32_t dstbase, int tid, int b, int kt,
    const __nv_bfloat16* __restrict__ kh, const __nv_bfloat16* __restrict__ kl,
    const __nv_bfloat16* __restrict__ vth, const __nv_bfloat16* __restrict__ vtl)
{
#pragma unroll
    for (int n = 0; n < 16; n++) {
        int i = tid + n * 128;
        int t = i >> 9, r = (i >> 3) & 63, c = i & 7;
        const __nv_bfloat16* src;
        if (t == 0)      src = kh  + ((size_t)b * LK_ + kt + r) * DO_ + c * 8;
        else if (t == 1) src = kl  + ((size_t)b * LK_ + kt + r) * DO_ + c * 8;
        else if (t == 2) src = vth + ((size_t)b * DO_ + r) * LK_ + kt + c * 8;
        else             src = vtl + ((size_t)b * DO_ + r) * LK_ + kt + c * 8;
        cp_async16(dstbase + t * TILE_B + r * RSTRIDE + c * 16, src);
    }
}

__global__ __launch_bounds__(128, 2) void attn_mma_kernel(
    const __nv_bfloat16* __restrict__ qh, const __nv_bfloat16* __restrict__ ql,
    const __nv_bfloat16* __restrict__ kh, const __nv_bfloat16* __restrict__ kl,
    const __nv_bfloat16* __restrict__ vth, const __nv_bfloat16* __restrict__ vtl,
    float* __restrict__ po, float* __restrict__ pl)
{
    extern __shared__ __align__(16) char sm[];
    const uint32_t sb = smem_u32(sm);

    const int tid = threadIdx.x;
    const int w = tid >> 5;
    const int lane = tid & 31;
    const int b = blockIdx.y;
    const int ks = blockIdx.z;
    const int it0 = ks * (LK_ / 128);
    const int it1 = it0 + (LK_ / 128);
    const size_t q0 = (size_t)blockIdx.x * 128;

#pragma unroll
    for (int n = 0; n < 16; n++) {
        int i = tid + n * 128;
        int t = i >> 10, r = (i >> 3) & 127, c = i & 7;
        const __nv_bfloat16* src =
            (t ? ql : qh) + ((size_t)b * LQ_ + q0 + r) * DO_ + c * 8;
        cp_async16(sb + (t ? O_QL : O_QH) + r * RSTRIDE + c * 16, src);
    }
    kv_load(sb + O_KV, tid, b, it0 * 64, kh, kl, vth, vtl);
    CP_COMMIT();
    CP_WAIT_ALL();
    __syncthreads();

    uint32_t qfh[2][4][4], qfl[2][4][4];
#pragma unroll
    for (int mi = 0; mi < 2; mi++) {
        int arow = 32 * w + 16 * mi + (lane & 7) + 8 * ((lane >> 3) & 1);
        int acol = 8 * (lane >> 4);
        uint32_t base = (uint32_t)(arow * RSTRIDE + acol * 2);
#pragma unroll
        for (int g = 0; g < 4; g++) {
            ldsm_x4(qfh[mi][g], sb + O_QH + base + 32 * g);
            ldsm_x4(qfl[mi][g], sb + O_QL + base + 32 * g);
        }
    }

    const uint32_t boff = (uint32_t)((lane & 7) * RSTRIDE + (lane >> 3) * 16);

    float oacc[2][8][4];
#pragma unroll
    for (int mi = 0; mi < 2; mi++)
#pragma unroll
        for (int j = 0; j < 8; j++)
#pragma unroll
            for (int c = 0; c < 4; c++) oacc[mi][j][c] = 0.f;
    float lsum[2][2] = {{0.f, 0.f}, {0.f, 0.f}};

    for (int it = it0; it < it1; it++) {
        const uint32_t kvb = sb + O_KV + (uint32_t)(it & 1) * KVBUF;
        if (it + 1 < it1) {
            kv_load(sb + O_KV + (uint32_t)((it + 1) & 1) * KVBUF,
                    tid, b, (it + 1) * 64, kh, kl, vth, vtl);
            CP_COMMIT();
        }

#pragma unroll 1
        for (int half = 0; half < 2; half++) {
            float sacc[2][4][4];
#pragma unroll
            for (int mi = 0; mi < 2; mi++)
#pragma unroll
                for (int jj = 0; jj < 4; jj++)
#pragma unroll
                    for (int c = 0; c < 4; c++) sacc[mi][jj][c] = 0.f;

#pragma unroll
            for (int jj = 0; jj < 4; jj++) {
                int j = 4 * half + jj;
                uint32_t bh[8], bl[8];
                uint32_t kb = kvb + j * (8 * RSTRIDE) + boff;
                ldsm_x4(bh, kb);
                ldsm_x4(bh + 4, kb + 64);
                uint32_t lb = kvb + TILE_B + j * (8 * RSTRIDE) + boff;
                ldsm_x4(bl, lb);
                ldsm_x4(bl + 4, lb + 64);
#pragma unroll
                for (int mi = 0; mi < 2; mi++)
#pragma unroll
                    for (int s = 0; s < 4; s++) {
                        mma16816(sacc[mi][jj], qfh[mi][s], bh[2 * s], bh[2 * s + 1]);
                        mma16816(sacc[mi][jj], qfh[mi][s], bl[2 * s], bl[2 * s + 1]);
                        mma16816(sacc[mi][jj], qfl[mi][s], bh[2 * s], bh[2 * s + 1]);
                    }
            }

            uint32_t pfh[2][2][4], pfl[2][2][4];
#pragma unroll
            for (int mi = 0; mi < 2; mi++)
#pragma unroll
                for (int sg = 0; sg < 2; sg++) {
                    float p[8];
                    p[0] = __expf(sacc[mi][2 * sg][0]);
                    p[1] = __expf(sacc[mi][2 * sg][1]);
                    p[2] = __expf(sacc[mi][2 * sg][2]);
                    p[3] = __expf(sacc[mi][2 * sg][3]);
                    p[4] = __expf(sacc[mi][2 * sg + 1][0]);
                    p[5] = __expf(sacc[mi][2 * sg + 1][1]);
                    p[6] = __expf(sacc[mi][2 * sg + 1][2]);
                    p[7] = __expf(sacc[mi][2 * sg + 1][3]);
                    lsum[mi][0] += (p[0] + p[1]) + (p[4] + p[5]);
                    lsum[mi][1] += (p[2] + p[3]) + (p[6] + p[7]);
#pragma unroll
                    for (int q = 0; q < 4; q++) {
                        uint32_t hp, lp;
                        split_pair(p[2 * q], p[2 * q + 1], hp, lp);
                        pfh[mi][sg][q] = hp;
                        pfl[mi][sg][q] = lp;
                    }
                }

#pragma unroll
            for (int j = 0; j < 8; j++) {
                uint32_t vh[4], vl[4];
                uint32_t vb = kvb + 2 * TILE_B + j * (8 * RSTRIDE) + half * 64 + boff;
                ldsm_x4(vh, vb);
                ldsm_x4(vl, vb + TILE_B);
#pragma unroll
                for (int mi = 0; mi < 2; mi++)
#pragma unroll
                    for (int sg = 0; sg < 2; sg++) {
                        mma16816(oacc[mi][j], pfh[mi][sg], vh[2 * sg], vh[2 * sg + 1]);
                        mma16816(oacc[mi][j], pfh[mi][sg], vl[2 * sg], vl[2 * sg + 1]);
                        mma16816(oacc[mi][j], pfl[mi][sg], vh[2 * sg], vh[2 * sg + 1]);
                    }
            }
        }

        CP_WAIT_ALL();
        __syncthreads();
    }

#pragma unroll
    for (int mi = 0; mi < 2; mi++) {
        float l0 = lsum[mi][0], l1 = lsum[mi][1];
        l0 += __shfl_xor_sync(0xffffffffu, l0, 1);
        l0 += __shfl_xor_sync(0xffffffffu, l0, 2);
        l1 += __shfl_xor_sync(0xffffffffu, l1, 1);
        l1 += __shfl_xor_sync(0xffffffffu, l1, 2);

        int row = 32 * w + 16 * mi + (lane >> 2);
        size_t rg = (size_t)b * LQ_ + q0 + row;
        float* ob = po + ((size_t)ks * NROW + rg) * DO_ + (lane & 3) * 2;
#pragma unroll
        for (int j = 0; j < 8; j++) {
            *(float2*)(ob + 8 * j) = make_float2(oacc[mi][j][0], oacc[mi][j][1]);
            *(float2*)(ob + 8 * j + 8 * DO_) = make_float2(oacc[mi][j][2], oacc[mi][j][3]);
        }
        if ((lane & 3) == 0) {
            pl[(size_t)ks * NROW + rg] = l0;
            pl[(size_t)ks * NROW + rg + 8] = l1;
        }
    }
}

// ---------------------------------------------------------------------------
__global__ __launch_bounds__(256) void reduce_kernel(
    const float* __restrict__ po, const float* __restrict__ pl,
    float* __restrict__ out)
{
    int idx = blockIdx.x * 256 + threadIdx.x;
    int row = idx >> 4;
    float inv = 1.0f / (pl[row] + pl[NROW + row]);
    const float4* p0 = (const float4*)po;
    float4 a = p0[idx];
    float4 b = p0[idx + NROW * DO_ / 4];
    float4 r = make_float4((a.x + b.x) * inv, (a.y + b.y) * inv,
                           (a.z + b.z) * inv, (a.w + b.w) * inv);
    ((float4*)out)[idx] = r;
}

// ---------------------------------------------------------------------------
extern "C" void kernel_launch(void* const* d_in, const int* in_sizes, int n_in,
                              void* d_out, int out_size)
{
    const float* query = (const float*)d_in[0];
    const float* key   = (const float*)d_in[1];
    const float* Wq    = (const float*)d_in[2];
    const float* Wk    = (const float*)d_in[3];
    const float* Wv    = (const float*)d_in[4];
    float* out = (float*)d_out;

    __nv_bfloat16 *qh, *ql, *khp, *klp, *vth, *vtl;
    float *po, *pl;
    cudaGetSymbolAddress((void**)&qh, g_qh);
    cudaGetSymbolAddress((void**)&ql, g_ql);
    cudaGetSymbolAddress((void**)&khp, g_kh);
    cudaGetSymbolAddress((void**)&klp, g_kl);
    cudaGetSymbolAddress((void**)&vth, g_vth);
    cudaGetSymbolAddress((void**)&vtl, g_vtl);
    cudaGetSymbolAddress((void**)&po, g_po);
    cudaGetSymbolAddress((void**)&pl, g_pl);

    cudaFuncSetAttribute(proj_mma_kernel,
                         cudaFuncAttributeMaxDynamicSharedMemorySize, PR_SMEM);
    proj_mma_kernel<<<384, 256, PR_SMEM>>>(query, key, Wq, Wk, Wv,
                                           qh, ql, khp, klp, vth, vtl);

    cudaFuncSetAttribute(attn_mma_kernel,
                         cudaFuncAttributeMaxDynamicSharedMemorySize, SM_BYTES);
    dim3 grid(LQ_ / 128, B_, 2);
    attn_mma_kernel<<<grid, 128, SM_BYTES>>>(qh, ql, khp, klp, vth, vtl, po, pl);

    reduce_kernel<<<(NROW * DO_ / 4) / 256, 256>>>(po, pl, out);
}